// round 1
// baseline (speedup 1.0000x reference)
#include <cuda_runtime.h>
#include <cstdint>

#define N_NODES 100000
#define N_EDGES 3200000
#define F_IN    512
#define F_H     128
#define F_OUT   40
#define K_ITERS 20
#define ALPHA   0.1f

// ---------------- scratch (device globals; no runtime allocation) ----------
__device__ float g_h1[(size_t)N_NODES * F_H];     // 51.2 MB
__device__ float g_h0[(size_t)N_NODES * F_OUT];   // 16 MB
__device__ float g_zA[(size_t)N_NODES * F_OUT];   // 16 MB
__device__ float g_zB[(size_t)N_NODES * F_OUT];   // 16 MB
__device__ float g_norm[N_EDGES];                 // 12.8 MB  ((1-alpha) * dinv[row]*dinv[col])
__device__ int   g_deg[N_NODES];
__device__ float g_dinv[N_NODES];
__device__ float g_selfc[N_NODES];                // (1-alpha) * dinv[i]^2

// ---------------- helpers ---------------------------------------------------
__device__ __forceinline__ void red_add_v4(float* p, float a, float b, float c, float d) {
    asm volatile("red.global.add.v4.f32 [%0], {%1, %2, %3, %4};"
                 :: "l"(p), "f"(a), "f"(b), "f"(c), "f"(d) : "memory");
}

// ---------------- prep kernels ----------------------------------------------
__global__ void k_deg_init() {
    int i = blockIdx.x * blockDim.x + threadIdx.x;
    if (i < N_NODES) g_deg[i] = 1;          // self-loop
}

__global__ void k_deg(const int* __restrict__ ei) {
    int e = blockIdx.x * blockDim.x + threadIdx.x;
    if (e < N_EDGES) atomicAdd(&g_deg[ei[N_EDGES + e]], 1);   // col = target
}

__global__ void k_dinv() {
    int i = blockIdx.x * blockDim.x + threadIdx.x;
    if (i >= N_NODES) return;
    float d = (float)g_deg[i];
    float r = rsqrtf(d);
    g_dinv[i]  = r;
    g_selfc[i] = (1.0f - ALPHA) * r * r;
}

__global__ void k_norm(const int* __restrict__ ei) {
    int e = blockIdx.x * blockDim.x + threadIdx.x;
    if (e >= N_EDGES) return;
    g_norm[e] = (1.0f - ALPHA) * g_dinv[ei[e]] * g_dinv[ei[N_EDGES + e]];
}

// ---------------- GEMM1: h1 = relu(x @ W1 + b1),  [N,512]@[512,128] ---------
__global__ void __launch_bounds__(256) k_gemm1(const float* __restrict__ x,
                                               const float* __restrict__ W1,
                                               const float* __restrict__ b1) {
    __shared__ float xs[32][128];
    int tid  = threadIdx.x;
    int col  = tid & 127;
    int rg   = tid >> 7;                 // 0 or 1
    int row0 = blockIdx.x * 32;          // N divisible by 32 (100000/32=3125)

    float acc[16];
#pragma unroll
    for (int r = 0; r < 16; r++) acc[r] = 0.0f;

    for (int kb = 0; kb < 4; kb++) {
        // cooperative load of 32x128 x-chunk (as float4)
#pragma unroll
        for (int i = 0; i < 4; i++) {
            int q  = tid + i * 256;      // 0..1023 float4 slots
            int r  = q >> 5;             // row within tile
            int c4 = q & 31;             // float4 column
            float4 v = *(const float4*)&x[(size_t)(row0 + r) * F_IN + kb * 128 + c4 * 4];
            *(float4*)&xs[r][c4 * 4] = v;
        }
        __syncthreads();
#pragma unroll 4
        for (int k = 0; k < 128; k++) {
            float w = W1[(size_t)(kb * 128 + k) * F_H + col];
#pragma unroll
            for (int r = 0; r < 16; r++)
                acc[r] = fmaf(xs[rg + 2 * r][k], w, acc[r]);
        }
        __syncthreads();
    }
    float bb = b1[col];
#pragma unroll
    for (int r = 0; r < 16; r++) {
        float v = acc[r] + bb;
        g_h1[(size_t)(row0 + rg + 2 * r) * F_H + col] = v > 0.0f ? v : 0.0f;
    }
}

// ---------------- GEMM2: h0 = relu(h1 @ W2 + b2), [N,128]@[128,40] ----------
__global__ void __launch_bounds__(320) k_gemm2(const float* __restrict__ W2,
                                               const float* __restrict__ b2) {
    __shared__ float hs[64][128];
    int tid  = threadIdx.x;
    int col  = tid % 40;
    int rg   = tid / 40;                 // 0..7
    int row0 = blockIdx.x * 64;

    // load 64x128 h1 tile (2048 float4)
    for (int q = tid; q < 2048; q += 320) {
        int r  = q >> 5;
        int c4 = q & 31;
        float4 v = make_float4(0.f, 0.f, 0.f, 0.f);
        if (row0 + r < N_NODES)
            v = *(const float4*)&g_h1[(size_t)(row0 + r) * F_H + c4 * 4];
        *(float4*)&hs[r][c4 * 4] = v;
    }
    __syncthreads();

    float acc[8];
#pragma unroll
    for (int r = 0; r < 8; r++) acc[r] = 0.0f;
#pragma unroll 4
    for (int k = 0; k < 128; k++) {
        float w = W2[(size_t)k * F_OUT + col];
#pragma unroll
        for (int r = 0; r < 8; r++)
            acc[r] = fmaf(hs[rg + 8 * r][k], w, acc[r]);
    }
    float bb = b2[col];
#pragma unroll
    for (int r = 0; r < 8; r++) {
        int row = row0 + rg + 8 * r;
        if (row < N_NODES) {
            float v = acc[r] + bb;
            g_h0[(size_t)row * F_OUT + col] = v > 0.0f ? v : 0.0f;
        }
    }
}

// ---------------- propagation: init dst = alpha*h0 + selfc*src --------------
__global__ void __launch_bounds__(256) k_selfinit(const float* __restrict__ src,
                                                  float* __restrict__ dst) {
    int q = blockIdx.x * blockDim.x + threadIdx.x;   // float4 index
    if (q >= N_NODES * (F_OUT / 4)) return;
    int i = q / (F_OUT / 4);
    float c = g_selfc[i];
    float4 h = ((const float4*)g_h0)[q];
    float4 s = ((const float4*)src)[q];
    float4 o;
    o.x = fmaf(c, s.x, ALPHA * h.x);
    o.y = fmaf(c, s.y, ALPHA * h.y);
    o.z = fmaf(c, s.z, ALPHA * h.z);
    o.w = fmaf(c, s.w, ALPHA * h.w);
    ((float4*)dst)[q] = o;
}

// ---------------- propagation: scatter edges via vectorized red -------------
__global__ void __launch_bounds__(256) k_edge(const int* __restrict__ ei,
                                              const float* __restrict__ src,
                                              float* __restrict__ dst) {
    int e = blockIdx.x * blockDim.x + threadIdx.x;
    if (e >= N_EDGES) return;
    int r = ei[e];
    int c = ei[N_EDGES + e];
    float w = g_norm[e];
    const float4* ps = (const float4*)(src + (size_t)r * F_OUT);
    float* pd = dst + (size_t)c * F_OUT;
    float4 v[F_OUT / 4];
#pragma unroll
    for (int q = 0; q < F_OUT / 4; q++) v[q] = __ldg(ps + q);
#pragma unroll
    for (int q = 0; q < F_OUT / 4; q++)
        red_add_v4(pd + q * 4, w * v[q].x, w * v[q].y, w * v[q].z, w * v[q].w);
}

// ---------------- launcher ---------------------------------------------------
extern "C" void kernel_launch(void* const* d_in, const int* in_sizes, int n_in,
                              void* d_out, int out_size) {
    const float* x  = (const float*)d_in[0];
    const int*   ei = (const int*)  d_in[1];
    const float* W1 = (const float*)d_in[2];
    const float* b1 = (const float*)d_in[3];
    const float* W2 = (const float*)d_in[4];
    const float* b2 = (const float*)d_in[5];
    float* out = (float*)d_out;

    float *zA, *zB, *h0;
    cudaGetSymbolAddress((void**)&zA, g_zA);
    cudaGetSymbolAddress((void**)&zB, g_zB);
    cudaGetSymbolAddress((void**)&h0, g_h0);

    k_deg_init<<<(N_NODES + 255) / 256, 256>>>();
    k_deg     <<<(N_EDGES + 255) / 256, 256>>>(ei);
    k_dinv    <<<(N_NODES + 255) / 256, 256>>>();
    k_norm    <<<(N_EDGES + 255) / 256, 256>>>(ei);

    k_gemm1<<<N_NODES / 32, 256>>>(x, W1, b1);
    k_gemm2<<<(N_NODES + 63) / 64, 320>>>(W2, b2);

    const float* src = h0;
    for (int it = 0; it < K_ITERS; it++) {
        float* dst = (it == K_ITERS - 1) ? out : ((it & 1) ? zB : zA);
        k_selfinit<<<(N_NODES * (F_OUT / 4) + 255) / 256, 256>>>(src, dst);
        k_edge    <<<(N_EDGES + 255) / 256, 256>>>(ei, src, dst);
        src = dst;
    }
}

// round 2
// speedup vs baseline: 2.8665x; 2.8665x over previous
#include <cuda_runtime.h>
#include <cstdint>

#define N_NODES 100000
#define N_EDGES 3200000
#define F_IN    512
#define F_H     128
#define F_OUT   40
#define K_ITERS 20
#define ALPHA   0.1f

#define SCAN_B  512
#define NBLK    ((N_NODES + SCAN_B - 1) / SCAN_B)   // 196

// ---------------- scratch (device globals; no runtime allocation) ----------
__device__ float g_h1[(size_t)N_NODES * F_H];     // 51.2 MB
__device__ float g_h0[(size_t)N_NODES * F_OUT];   // 16 MB
__device__ float g_zA[(size_t)N_NODES * F_OUT];   // 16 MB
__device__ float g_zB[(size_t)N_NODES * F_OUT];   // 16 MB
__device__ int   g_cnt[N_NODES];
__device__ int   g_offs[N_NODES + 1];
__device__ int   g_cursor[N_NODES];
__device__ int   g_bsum[NBLK];
__device__ int   g_bsum2[NBLK];
__device__ float g_dinv[N_NODES];
__device__ float g_selfc[N_NODES];                // (1-alpha) * dinv[i]^2
__device__ int   g_csr_idx[N_EDGES];              // source row * 10 (premultiplied)
__device__ float g_csr_w[N_EDGES];                // (1-alpha)*dinv[r]*dinv[c]

// ---------------- prep kernels ----------------------------------------------
__global__ void k_zero() {
    int i = blockIdx.x * blockDim.x + threadIdx.x;
    if (i < N_NODES) g_cnt[i] = 0;
}

__global__ void k_count(const int* __restrict__ ei) {
    int e = blockIdx.x * blockDim.x + threadIdx.x;
    if (e < N_EDGES) atomicAdd(&g_cnt[ei[N_EDGES + e]], 1);
}

__global__ void k_dinv() {
    int i = blockIdx.x * blockDim.x + threadIdx.x;
    if (i >= N_NODES) return;
    float d = (float)(g_cnt[i] + 1);      // +1 self-loop
    float r = rsqrtf(d);
    g_dinv[i]  = r;
    g_selfc[i] = (1.0f - ALPHA) * r * r;
}

// ---- exclusive scan of g_cnt into g_offs (3 stages) ----
__global__ void k_scan1() {
    __shared__ int s[SCAN_B];
    int i = blockIdx.x * SCAN_B + threadIdx.x;
    int v = (i < N_NODES) ? g_cnt[i] : 0;
    s[threadIdx.x] = v;
    __syncthreads();
#pragma unroll
    for (int off = 1; off < SCAN_B; off <<= 1) {
        int t = (threadIdx.x >= off) ? s[threadIdx.x - off] : 0;
        __syncthreads();
        s[threadIdx.x] += t;
        __syncthreads();
    }
    if (i < N_NODES) g_offs[i] = s[threadIdx.x] - v;   // exclusive
    if (threadIdx.x == SCAN_B - 1) g_bsum[blockIdx.x] = s[SCAN_B - 1];
}

__global__ void k_scan2() {
    __shared__ int s[NBLK];
    __shared__ int so[NBLK + 1];
    int t = threadIdx.x;
    if (t < NBLK) s[t] = g_bsum[t];
    __syncthreads();
    if (t == 0) {
        int acc = 0;
        for (int b = 0; b < NBLK; b++) { so[b] = acc; acc += s[b]; }
        so[NBLK] = acc;
    }
    __syncthreads();
    if (t < NBLK) g_bsum2[t] = so[t];
    if (t == 0) g_offs[N_NODES] = so[NBLK];
}

__global__ void k_scan3() {
    int i = blockIdx.x * blockDim.x + threadIdx.x;
    if (i >= N_NODES) return;
    int o = g_offs[i] + g_bsum2[i / SCAN_B];
    g_offs[i]   = o;
    g_cursor[i] = o;
}

__global__ void k_fill(const int* __restrict__ ei) {
    int e = blockIdx.x * blockDim.x + threadIdx.x;
    if (e >= N_EDGES) return;
    int r = ei[e];
    int c = ei[N_EDGES + e];
    int pos = atomicAdd(&g_cursor[c], 1);
    g_csr_idx[pos] = r * (F_OUT / 4);                       // premultiplied float4-row index
    g_csr_w[pos]   = (1.0f - ALPHA) * g_dinv[r] * g_dinv[c];
}

// ---------------- GEMM1: h1 = relu(x @ W1 + b1),  [N,512]@[512,128] ---------
__global__ void __launch_bounds__(256) k_gemm1(const float* __restrict__ x,
                                               const float* __restrict__ W1,
                                               const float* __restrict__ b1) {
    __shared__ float xs[32][128];
    int tid  = threadIdx.x;
    int col  = tid & 127;
    int rg   = tid >> 7;
    int row0 = blockIdx.x * 32;

    float acc[16];
#pragma unroll
    for (int r = 0; r < 16; r++) acc[r] = 0.0f;

    for (int kb = 0; kb < 4; kb++) {
#pragma unroll
        for (int i = 0; i < 4; i++) {
            int q  = tid + i * 256;
            int r  = q >> 5;
            int c4 = q & 31;
            float4 v = *(const float4*)&x[(size_t)(row0 + r) * F_IN + kb * 128 + c4 * 4];
            *(float4*)&xs[r][c4 * 4] = v;
        }
        __syncthreads();
#pragma unroll 4
        for (int k = 0; k < 128; k++) {
            float w = W1[(size_t)(kb * 128 + k) * F_H + col];
#pragma unroll
            for (int r = 0; r < 16; r++)
                acc[r] = fmaf(xs[rg + 2 * r][k], w, acc[r]);
        }
        __syncthreads();
    }
    float bb = b1[col];
#pragma unroll
    for (int r = 0; r < 16; r++) {
        float v = acc[r] + bb;
        g_h1[(size_t)(row0 + rg + 2 * r) * F_H + col] = v > 0.0f ? v : 0.0f;
    }
}

// ---------------- GEMM2: h0 = relu(h1 @ W2 + b2), [N,128]@[128,40] ----------
__global__ void __launch_bounds__(320) k_gemm2(const float* __restrict__ W2,
                                               const float* __restrict__ b2) {
    __shared__ float hs[64][128];
    int tid  = threadIdx.x;
    int col  = tid % 40;
    int rg   = tid / 40;
    int row0 = blockIdx.x * 64;

    for (int q = tid; q < 2048; q += 320) {
        int r  = q >> 5;
        int c4 = q & 31;
        float4 v = make_float4(0.f, 0.f, 0.f, 0.f);
        if (row0 + r < N_NODES)
            v = *(const float4*)&g_h1[(size_t)(row0 + r) * F_H + c4 * 4];
        *(float4*)&hs[r][c4 * 4] = v;
    }
    __syncthreads();

    float acc[8];
#pragma unroll
    for (int r = 0; r < 8; r++) acc[r] = 0.0f;
#pragma unroll 4
    for (int k = 0; k < 128; k++) {
        float w = W2[(size_t)k * F_OUT + col];
#pragma unroll
        for (int r = 0; r < 8; r++)
            acc[r] = fmaf(hs[rg + 8 * r][k], w, acc[r]);
    }
    float bb = b2[col];
#pragma unroll
    for (int r = 0; r < 8; r++) {
        int row = row0 + rg + 8 * r;
        if (row < N_NODES) {
            float v = acc[r] + bb;
            g_h0[(size_t)row * F_OUT + col] = v > 0.0f ? v : 0.0f;
        }
    }
}

// ---------------- propagation: pull-mode CSR aggregation --------------------
// 10 threads per node; thread q owns float4 chunk q of the 40-dim feature.
// dst[c] = alpha*h0[c] + selfc[c]*src[c] + sum_e w[e]*src[csr_idx[e]]
__global__ void __launch_bounds__(320) k_pull(const float* __restrict__ src,
                                              float* __restrict__ dst) {
    int tid  = threadIdx.x;
    int node = blockIdx.x * 32 + tid / 10;     // 32 nodes per block, exact grid
    int q    = tid % 10;

    const float4* s4 = (const float4*)src;
    const float4* h4 = (const float4*)g_h0;

    float sc = g_selfc[node];
    float4 h = h4[node * 10 + q];
    float4 s = s4[node * 10 + q];
    float4 acc;
    acc.x = fmaf(sc, s.x, ALPHA * h.x);
    acc.y = fmaf(sc, s.y, ALPHA * h.y);
    acc.z = fmaf(sc, s.z, ALPHA * h.z);
    acc.w = fmaf(sc, s.w, ALPHA * h.w);

    int e   = g_offs[node];
    int end = g_offs[node + 1];

    for (; e + 4 <= end; e += 4) {
        int   r0 = g_csr_idx[e],     r1 = g_csr_idx[e + 1];
        int   r2 = g_csr_idx[e + 2], r3 = g_csr_idx[e + 3];
        float w0 = g_csr_w[e],       w1 = g_csr_w[e + 1];
        float w2 = g_csr_w[e + 2],   w3 = g_csr_w[e + 3];
        float4 v0 = __ldg(&s4[r0 + q]);
        float4 v1 = __ldg(&s4[r1 + q]);
        float4 v2 = __ldg(&s4[r2 + q]);
        float4 v3 = __ldg(&s4[r3 + q]);
        acc.x = fmaf(w0, v0.x, acc.x); acc.y = fmaf(w0, v0.y, acc.y);
        acc.z = fmaf(w0, v0.z, acc.z); acc.w = fmaf(w0, v0.w, acc.w);
        acc.x = fmaf(w1, v1.x, acc.x); acc.y = fmaf(w1, v1.y, acc.y);
        acc.z = fmaf(w1, v1.z, acc.z); acc.w = fmaf(w1, v1.w, acc.w);
        acc.x = fmaf(w2, v2.x, acc.x); acc.y = fmaf(w2, v2.y, acc.y);
        acc.z = fmaf(w2, v2.z, acc.z); acc.w = fmaf(w2, v2.w, acc.w);
        acc.x = fmaf(w3, v3.x, acc.x); acc.y = fmaf(w3, v3.y, acc.y);
        acc.z = fmaf(w3, v3.z, acc.z); acc.w = fmaf(w3, v3.w, acc.w);
    }
    for (; e < end; e++) {
        int   r = g_csr_idx[e];
        float w = g_csr_w[e];
        float4 v = __ldg(&s4[r + q]);
        acc.x = fmaf(w, v.x, acc.x); acc.y = fmaf(w, v.y, acc.y);
        acc.z = fmaf(w, v.z, acc.z); acc.w = fmaf(w, v.w, acc.w);
    }
    ((float4*)dst)[node * 10 + q] = acc;
}

// ---------------- launcher ---------------------------------------------------
extern "C" void kernel_launch(void* const* d_in, const int* in_sizes, int n_in,
                              void* d_out, int out_size) {
    const float* x  = (const float*)d_in[0];
    const int*   ei = (const int*)  d_in[1];
    const float* W1 = (const float*)d_in[2];
    const float* b1 = (const float*)d_in[3];
    const float* W2 = (const float*)d_in[4];
    const float* b2 = (const float*)d_in[5];
    float* out = (float*)d_out;

    float *zA, *zB, *h0;
    cudaGetSymbolAddress((void**)&zA, g_zA);
    cudaGetSymbolAddress((void**)&zB, g_zB);
    cudaGetSymbolAddress((void**)&h0, g_h0);

    // CSR build
    k_zero <<<(N_NODES + 255) / 256, 256>>>();
    k_count<<<(N_EDGES + 255) / 256, 256>>>(ei);
    k_dinv <<<(N_NODES + 255) / 256, 256>>>();
    k_scan1<<<NBLK, SCAN_B>>>();
    k_scan2<<<1, 256>>>();
    k_scan3<<<(N_NODES + 255) / 256, 256>>>();
    k_fill <<<(N_EDGES + 255) / 256, 256>>>(ei);

    // MLP encoder
    k_gemm1<<<N_NODES / 32, 256>>>(x, W1, b1);
    k_gemm2<<<(N_NODES + 63) / 64, 320>>>(W2, b2);

    // APPNP propagation (pull mode)
    const float* src = h0;
    for (int it = 0; it < K_ITERS; it++) {
        float* dst = (it == K_ITERS - 1) ? out : ((it & 1) ? zB : zA);
        k_pull<<<N_NODES / 32, 320>>>(src, dst);
        src = dst;
    }
}

// round 4
// speedup vs baseline: 3.6744x; 1.2818x over previous
#include <cuda_runtime.h>
#include <cstdint>

#define N_NODES 100000
#define N_EDGES 3200000
#define F_IN    512
#define F_H     128
#define F_OUT   40
#define K_ITERS 20
#define ALPHA   0.1f

#define SCAN_B  512
#define NBLK    ((N_NODES + SCAN_B - 1) / SCAN_B)   // 196

// ---------------- scratch (device globals; no runtime allocation) ----------
__device__ float g_h1[(size_t)N_NODES * F_H];     // 51.2 MB
__device__ float g_W1T_hi[(size_t)F_H * F_IN];    // 256 KB  (tf32 hi part, [n][k])
__device__ float g_W1T_lo[(size_t)F_H * F_IN];    // 256 KB  (tf32 lo part)
__device__ float g_h0[(size_t)N_NODES * F_OUT];   // 16 MB
__device__ float g_zA[(size_t)N_NODES * F_OUT];   // 16 MB
__device__ float g_zB[(size_t)N_NODES * F_OUT];   // 16 MB
__device__ int   g_cnt[N_NODES];
__device__ int   g_offs[N_NODES + 1];
__device__ int   g_cursor[N_NODES];
__device__ int   g_bsum[NBLK];
__device__ int   g_bsum2[NBLK];
__device__ float g_dinv[N_NODES];
__device__ float g_selfc[N_NODES];                // (1-alpha) * dinv[i]^2
__device__ int2  g_csr[N_EDGES];                  // {src_row*10, float_bits(w)}

// ---------------- helpers ----------------------------------------------------
__device__ __forceinline__ float tf32_rna(float v) {
    uint32_t r;
    asm("cvt.rna.tf32.f32 %0, %1;" : "=r"(r) : "f"(v));
    return __uint_as_float(r);
}
__device__ __forceinline__ void cp16(uint32_t s, const void* g) {
    asm volatile("cp.async.cg.shared.global [%0], [%1], 16;" :: "r"(s), "l"(g));
}
__device__ __forceinline__ uint32_t smem_u32(const void* p) {
    uint32_t a;
    asm("{ .reg .u64 t; cvta.to.shared.u64 t, %1; cvt.u32.u64 %0, t; }" : "=r"(a) : "l"(p));
    return a;
}
__device__ __forceinline__ void mma_tf32(float* c, const float* a, const float* b) {
    asm volatile(
        "mma.sync.aligned.m16n8k8.row.col.f32.tf32.tf32.f32 "
        "{%0,%1,%2,%3}, {%4,%5,%6,%7}, {%8,%9}, {%0,%1,%2,%3};"
        : "+f"(c[0]), "+f"(c[1]), "+f"(c[2]), "+f"(c[3])
        : "r"(__float_as_uint(a[0])), "r"(__float_as_uint(a[1])),
          "r"(__float_as_uint(a[2])), "r"(__float_as_uint(a[3])),
          "r"(__float_as_uint(b[0])), "r"(__float_as_uint(b[1])));
}

// ---------------- prep kernels ----------------------------------------------
__global__ void k_zero() {
    int i = blockIdx.x * blockDim.x + threadIdx.x;
    if (i < N_NODES) g_cnt[i] = 0;
}
__global__ void k_count(const int* __restrict__ ei) {
    int e = blockIdx.x * blockDim.x + threadIdx.x;
    if (e < N_EDGES) atomicAdd(&g_cnt[ei[N_EDGES + e]], 1);
}
__global__ void k_dinv() {
    int i = blockIdx.x * blockDim.x + threadIdx.x;
    if (i >= N_NODES) return;
    float d = (float)(g_cnt[i] + 1);
    float r = rsqrtf(d);
    g_dinv[i]  = r;
    g_selfc[i] = (1.0f - ALPHA) * r * r;
}
__global__ void k_scan1() {
    __shared__ int s[SCAN_B];
    int i = blockIdx.x * SCAN_B + threadIdx.x;
    int v = (i < N_NODES) ? g_cnt[i] : 0;
    s[threadIdx.x] = v;
    __syncthreads();
#pragma unroll
    for (int off = 1; off < SCAN_B; off <<= 1) {
        int t = (threadIdx.x >= off) ? s[threadIdx.x - off] : 0;
        __syncthreads();
        s[threadIdx.x] += t;
        __syncthreads();
    }
    if (i < N_NODES) g_offs[i] = s[threadIdx.x] - v;
    if (threadIdx.x == SCAN_B - 1) g_bsum[blockIdx.x] = s[SCAN_B - 1];
}
__global__ void k_scan2() {
    __shared__ int s[NBLK];
    __shared__ int so[NBLK + 1];
    int t = threadIdx.x;
    if (t < NBLK) s[t] = g_bsum[t];
    __syncthreads();
    if (t == 0) {
        int acc = 0;
        for (int b = 0; b < NBLK; b++) { so[b] = acc; acc += s[b]; }
        so[NBLK] = acc;
    }
    __syncthreads();
    if (t < NBLK) g_bsum2[t] = so[t];
    if (t == 0) g_offs[N_NODES] = so[NBLK];
}
__global__ void k_scan3() {
    int i = blockIdx.x * blockDim.x + threadIdx.x;
    if (i >= N_NODES) return;
    int o = g_offs[i] + g_bsum2[i / SCAN_B];
    g_offs[i]   = o;
    g_cursor[i] = o;
}
__global__ void k_fill(const int* __restrict__ ei) {
    int e = blockIdx.x * blockDim.x + threadIdx.x;
    if (e >= N_EDGES) return;
    int r = ei[e];
    int c = ei[N_EDGES + e];
    int pos = atomicAdd(&g_cursor[c], 1);
    float w = (1.0f - ALPHA) * g_dinv[r] * g_dinv[c];
    g_csr[pos] = make_int2(r * (F_OUT / 4), __float_as_int(w));
}
__global__ void k_w1t(const float* __restrict__ W1) {
    int i = blockIdx.x * blockDim.x + threadIdx.x;   // i = k*128+n
    if (i >= F_IN * F_H) return;
    int k = i >> 7, n = i & 127;
    float v  = W1[i];
    float hi = tf32_rna(v);
    g_W1T_hi[(size_t)n * F_IN + k] = hi;
    g_W1T_lo[(size_t)n * F_IN + k] = tf32_rna(v - hi);
}

// ---------------- GEMM1 via mma.sync tf32x3 ---------------------------------
// h1 = relu(x @ W1 + b1). Block tile 128x128, BK=32, 8 warps (4M x 2N).
// x split into tf32 hi/lo in-kernel; W pre-split. acc += xh*wh + xh*wl + xl*wh.
#define GST    36                                   // smem row stride (floats)
#define GARR   (128 * GST)                          // one array: 4608 floats
#define GSMEM  (4 * GARR * 4)                       // 73728 bytes

__global__ void __launch_bounds__(256) k_gemm1_mma(const float* __restrict__ x,
                                                   const float* __restrict__ b1) {
    extern __shared__ float sm[];
    float* xs_h = sm;
    float* xs_l = sm + GARR;
    float* ws_h = sm + 2 * GARR;
    float* ws_l = sm + 3 * GARR;
    uint32_t ws_h32 = smem_u32(ws_h);
    uint32_t ws_l32 = smem_u32(ws_l);

    int tid  = threadIdx.x;
    int wid  = tid >> 5, lid = tid & 31;
    int gid  = lid >> 2, tig = lid & 3;
    int wm   = wid & 3, wn = wid >> 2;              // 4 x 2 warp grid
    int row0 = blockIdx.x * 128;

    float acc[2][8][4];
#pragma unroll
    for (int mt = 0; mt < 2; mt++)
#pragma unroll
        for (int nt = 0; nt < 8; nt++)
#pragma unroll
            for (int i = 0; i < 4; i++) acc[mt][nt][i] = 0.0f;

    for (int kt = 0; kt < 16; kt++) {
        // ---- fill W tiles via cp.async (pre-split hi/lo) ----
#pragma unroll
        for (int i = 0; i < 4; i++) {
            int slot = tid + i * 256;               // 0..1023
            int n  = slot >> 3;
            int c4 = slot & 7;
            const float* src = &g_W1T_hi[(size_t)n * F_IN + kt * 32 + c4 * 4];
            cp16(ws_h32 + (n * GST + c4 * 4) * 4, src);
            cp16(ws_l32 + (n * GST + c4 * 4) * 4, src + (size_t)F_H * F_IN);
        }
        asm volatile("cp.async.commit_group;" ::: "memory");
        // ---- fill x tiles: LDG -> tf32 split -> STS ----
#pragma unroll
        for (int i = 0; i < 4; i++) {
            int slot = tid + i * 256;
            int m  = slot >> 3;
            int c4 = slot & 7;
            int grow = row0 + m; if (grow >= N_NODES) grow = N_NODES - 1;
            float4 v = *(const float4*)&x[(size_t)grow * F_IN + kt * 32 + c4 * 4];
            float4 h, l;
            h.x = tf32_rna(v.x); l.x = tf32_rna(v.x - h.x);
            h.y = tf32_rna(v.y); l.y = tf32_rna(v.y - h.y);
            h.z = tf32_rna(v.z); l.z = tf32_rna(v.z - h.z);
            h.w = tf32_rna(v.w); l.w = tf32_rna(v.w - h.w);
            *(float4*)&xs_h[m * GST + c4 * 4] = h;
            *(float4*)&xs_l[m * GST + c4 * 4] = l;
        }
        asm volatile("cp.async.wait_group 0;" ::: "memory");
        __syncthreads();

        // ---- compute: 4 k-steps of 8 ----
#pragma unroll
        for (int ks = 0; ks < 4; ks++) {
            int kk = ks * 8;
            float ah[2][4], al[2][4];
#pragma unroll
            for (int mt = 0; mt < 2; mt++) {
                int m = wm * 32 + mt * 16 + gid;
                ah[mt][0] = xs_h[m * GST + kk + tig];
                ah[mt][1] = xs_h[(m + 8) * GST + kk + tig];
                ah[mt][2] = xs_h[m * GST + kk + tig + 4];
                ah[mt][3] = xs_h[(m + 8) * GST + kk + tig + 4];
                al[mt][0] = xs_l[m * GST + kk + tig];
                al[mt][1] = xs_l[(m + 8) * GST + kk + tig];
                al[mt][2] = xs_l[m * GST + kk + tig + 4];
                al[mt][3] = xs_l[(m + 8) * GST + kk + tig + 4];
            }
#pragma unroll
            for (int nt = 0; nt < 8; nt++) {
                int n = wn * 64 + nt * 8 + gid;
                float bh[2], bl[2];
                bh[0] = ws_h[n * GST + kk + tig];
                bh[1] = ws_h[n * GST + kk + tig + 4];
                bl[0] = ws_l[n * GST + kk + tig];
                bl[1] = ws_l[n * GST + kk + tig + 4];
#pragma unroll
                for (int mt = 0; mt < 2; mt++) {
                    mma_tf32(acc[mt][nt], ah[mt], bh);
                    mma_tf32(acc[mt][nt], ah[mt], bl);
                    mma_tf32(acc[mt][nt], al[mt], bh);
                }
            }
        }
        __syncthreads();
    }

    // ---- epilogue: bias + relu + store ----
#pragma unroll
    for (int nt = 0; nt < 8; nt++) {
        int col = wn * 64 + nt * 8 + tig * 2;
        float2 bb = *(const float2*)&b1[col];
#pragma unroll
        for (int mt = 0; mt < 2; mt++) {
            int r0 = row0 + wm * 32 + mt * 16 + gid;
            if (r0 < N_NODES) {
                float2 o;
                o.x = acc[mt][nt][0] + bb.x;  o.y = acc[mt][nt][1] + bb.y;
                o.x = o.x > 0.f ? o.x : 0.f;  o.y = o.y > 0.f ? o.y : 0.f;
                *(float2*)&g_h1[(size_t)r0 * F_H + col] = o;
            }
            if (r0 + 8 < N_NODES) {
                float2 o;
                o.x = acc[mt][nt][2] + bb.x;  o.y = acc[mt][nt][3] + bb.y;
                o.x = o.x > 0.f ? o.x : 0.f;  o.y = o.y > 0.f ? o.y : 0.f;
                *(float2*)&g_h1[(size_t)(r0 + 8) * F_H + col] = o;
            }
        }
    }
}

// ---------------- GEMM2: h0 = relu(h1 @ W2 + b2), [N,128]@[128,40] ----------
__global__ void __launch_bounds__(320) k_gemm2(const float* __restrict__ W2,
                                               const float* __restrict__ b2) {
    __shared__ float hs[64][128];
    int tid  = threadIdx.x;
    int col  = tid % 40;
    int rg   = tid / 40;
    int row0 = blockIdx.x * 64;

    for (int q = tid; q < 2048; q += 320) {
        int r  = q >> 5;
        int c4 = q & 31;
        float4 v = make_float4(0.f, 0.f, 0.f, 0.f);
        if (row0 + r < N_NODES)
            v = *(const float4*)&g_h1[(size_t)(row0 + r) * F_H + c4 * 4];
        *(float4*)&hs[r][c4 * 4] = v;
    }
    __syncthreads();

    float acc[8];
#pragma unroll
    for (int r = 0; r < 8; r++) acc[r] = 0.0f;
#pragma unroll 4
    for (int k = 0; k < 128; k++) {
        float w = W2[(size_t)k * F_OUT + col];
#pragma unroll
        for (int r = 0; r < 8; r++)
            acc[r] = fmaf(hs[rg + 8 * r][k], w, acc[r]);
    }
    float bb = b2[col];
#pragma unroll
    for (int r = 0; r < 8; r++) {
        int row = row0 + rg + 8 * r;
        if (row < N_NODES) {
            float v = acc[r] + bb;
            g_h0[(size_t)row * F_OUT + col] = v > 0.0f ? v : 0.0f;
        }
    }
}

// ---------------- propagation: pull-mode CSR, smem-staged edges -------------
#define PTILE 2048
__global__ void __launch_bounds__(320) k_pull(const float* __restrict__ src,
                                              float* __restrict__ dst) {
    __shared__ int2 se[PTILE];
    int tid  = threadIdx.x;
    int g    = tid / 10;
    int q    = tid % 10;
    int node = blockIdx.x * 32 + g;

    const float4* s4 = (const float4*)src;
    const float4* h4 = (const float4*)g_h0;

    float sc = g_selfc[node];
    float4 h = h4[node * 10 + q];
    float4 s = s4[node * 10 + q];
    float4 acc;
    acc.x = fmaf(sc, s.x, ALPHA * h.x);
    acc.y = fmaf(sc, s.y, ALPHA * h.y);
    acc.z = fmaf(sc, s.z, ALPHA * h.z);
    acc.w = fmaf(sc, s.w, ALPHA * h.w);

    int base   = g_offs[blockIdx.x * 32];
    int endAll = g_offs[blockIdx.x * 32 + 32];
    int e0 = g_offs[node];
    int e1 = g_offs[node + 1];

    for (int t0 = base; t0 < endAll; t0 += PTILE) {
        int cnt = min(PTILE, endAll - t0);
        __syncthreads();
        for (int i = tid; i < cnt; i += 320) se[i] = g_csr[t0 + i];
        __syncthreads();
        int eb = max(e0, t0) - t0;
        int ee = min(e1, t0 + cnt) - t0;
        int e = eb;
        for (; e + 2 <= ee; e += 2) {
            int2 p0 = se[e], p1 = se[e + 1];
            float4 v0 = __ldg(&s4[p0.x + q]);
            float4 v1 = __ldg(&s4[p1.x + q]);
            float w0 = __int_as_float(p0.y), w1 = __int_as_float(p1.y);
            acc.x = fmaf(w0, v0.x, acc.x); acc.y = fmaf(w0, v0.y, acc.y);
            acc.z = fmaf(w0, v0.z, acc.z); acc.w = fmaf(w0, v0.w, acc.w);
            acc.x = fmaf(w1, v1.x, acc.x); acc.y = fmaf(w1, v1.y, acc.y);
            acc.z = fmaf(w1, v1.z, acc.z); acc.w = fmaf(w1, v1.w, acc.w);
        }
        if (e < ee) {
            int2 p = se[e];
            float4 v = __ldg(&s4[p.x + q]);
            float w = __int_as_float(p.y);
            acc.x = fmaf(w, v.x, acc.x); acc.y = fmaf(w, v.y, acc.y);
            acc.z = fmaf(w, v.z, acc.z); acc.w = fmaf(w, v.w, acc.w);
        }
    }
    ((float4*)dst)[node * 10 + q] = acc;
}

// ---------------- launcher ---------------------------------------------------
extern "C" void kernel_launch(void* const* d_in, const int* in_sizes, int n_in,
                              void* d_out, int out_size) {
    const float* x  = (const float*)d_in[0];
    const int*   ei = (const int*)  d_in[1];
    const float* W1 = (const float*)d_in[2];
    const float* b1 = (const float*)d_in[3];
    const float* W2 = (const float*)d_in[4];
    const float* b2 = (const float*)d_in[5];
    float* out = (float*)d_out;

    float *zA, *zB, *h0;
    cudaGetSymbolAddress((void**)&zA, g_zA);
    cudaGetSymbolAddress((void**)&zB, g_zB);
    cudaGetSymbolAddress((void**)&h0, g_h0);

    cudaFuncSetAttribute(k_gemm1_mma, cudaFuncAttributeMaxDynamicSharedMemorySize, GSMEM);

    // CSR build
    k_zero <<<(N_NODES + 255) / 256, 256>>>();
    k_count<<<(N_EDGES + 255) / 256, 256>>>(ei);
    k_dinv <<<(N_NODES + 255) / 256, 256>>>();
    k_scan1<<<NBLK, SCAN_B>>>();
    k_scan2<<<1, 256>>>();
    k_scan3<<<(N_NODES + 255) / 256, 256>>>();
    k_fill <<<(N_EDGES + 255) / 256, 256>>>(ei);

    // MLP encoder
    k_w1t<<<(F_IN * F_H + 255) / 256, 256>>>(W1);
    k_gemm1_mma<<<(N_NODES + 127) / 128, 256, GSMEM>>>(x, b1);
    k_gemm2<<<(N_NODES + 63) / 64, 320>>>(W2, b2);

    // APPNP propagation (pull mode)
    const float* src = h0;
    for (int it = 0; it < K_ITERS; it++) {
        float* dst = (it == K_ITERS - 1) ? out : ((it & 1) ? zB : zA);
        k_pull<<<N_NODES / 32, 320>>>(src, dst);
        src = dst;
    }
}

// round 5
// speedup vs baseline: 3.8393x; 1.0449x over previous
#include <cuda_runtime.h>
#include <cuda_fp16.h>
#include <cstdint>

#define N_NODES 100000
#define N_EDGES 3200000
#define F_IN    512
#define F_H     128
#define F_OUT   40
#define K_ITERS 20
#define ALPHA   0.1f

#define SCAN_B  512
#define NBLK    ((N_NODES + SCAN_B - 1) / SCAN_B)   // 196

// ---------------- scratch (device globals; no runtime allocation) ----------
__device__ float  g_h1[(size_t)N_NODES * F_H];     // 51.2 MB
__device__ float  g_W1T_hi[(size_t)F_H * F_IN];
__device__ float  g_W1T_lo[(size_t)F_H * F_IN];
__device__ __half g_h0h[(size_t)N_NODES * F_OUT];  // 8 MB  (fp16 h0)
__device__ __half g_zhA[(size_t)N_NODES * F_OUT];  // 8 MB
__device__ __half g_zhB[(size_t)N_NODES * F_OUT];  // 8 MB
__device__ int    g_cnt[N_NODES];
__device__ int    g_offs[N_NODES + 1];
__device__ int    g_cursor[N_NODES];
__device__ int    g_bsum[NBLK];
__device__ int    g_bsum2[NBLK];
__device__ float  g_dinv[N_NODES];
__device__ float  g_selfc[N_NODES];                // (1-alpha) * dinv[i]^2
__device__ int2   g_csr[N_EDGES];                  // {src_row*5 (uint4 units), float_bits(w)}

// ---------------- helpers ----------------------------------------------------
__device__ __forceinline__ float tf32_rna(float v) {
    uint32_t r;
    asm("cvt.rna.tf32.f32 %0, %1;" : "=r"(r) : "f"(v));
    return __uint_as_float(r);
}
__device__ __forceinline__ void cp16(uint32_t s, const void* g) {
    asm volatile("cp.async.cg.shared.global [%0], [%1], 16;" :: "r"(s), "l"(g));
}
__device__ __forceinline__ uint32_t smem_u32(const void* p) {
    uint32_t a;
    asm("{ .reg .u64 t; cvta.to.shared.u64 t, %1; cvt.u32.u64 %0, t; }" : "=r"(a) : "l"(p));
    return a;
}
__device__ __forceinline__ void mma_tf32(float* c, const float* a, const float* b) {
    asm volatile(
        "mma.sync.aligned.m16n8k8.row.col.f32.tf32.tf32.f32 "
        "{%0,%1,%2,%3}, {%4,%5,%6,%7}, {%8,%9}, {%0,%1,%2,%3};"
        : "+f"(c[0]), "+f"(c[1]), "+f"(c[2]), "+f"(c[3])
        : "r"(__float_as_uint(a[0])), "r"(__float_as_uint(a[1])),
          "r"(__float_as_uint(a[2])), "r"(__float_as_uint(a[3])),
          "r"(__float_as_uint(b[0])), "r"(__float_as_uint(b[1])));
}

// ---------------- prep kernels ----------------------------------------------
__global__ void k_zero() {
    int i = blockIdx.x * blockDim.x + threadIdx.x;
    if (i < N_NODES) g_cnt[i] = 0;
}
__global__ void k_count(const int* __restrict__ ei) {
    int e = blockIdx.x * blockDim.x + threadIdx.x;
    if (e < N_EDGES) atomicAdd(&g_cnt[ei[N_EDGES + e]], 1);
}
__global__ void k_dinv() {
    int i = blockIdx.x * blockDim.x + threadIdx.x;
    if (i >= N_NODES) return;
    float d = (float)(g_cnt[i] + 1);
    float r = rsqrtf(d);
    g_dinv[i]  = r;
    g_selfc[i] = (1.0f - ALPHA) * r * r;
}
__global__ void k_scan1() {
    __shared__ int s[SCAN_B];
    int i = blockIdx.x * SCAN_B + threadIdx.x;
    int v = (i < N_NODES) ? g_cnt[i] : 0;
    s[threadIdx.x] = v;
    __syncthreads();
#pragma unroll
    for (int off = 1; off < SCAN_B; off <<= 1) {
        int t = (threadIdx.x >= off) ? s[threadIdx.x - off] : 0;
        __syncthreads();
        s[threadIdx.x] += t;
        __syncthreads();
    }
    if (i < N_NODES) g_offs[i] = s[threadIdx.x] - v;
    if (threadIdx.x == SCAN_B - 1) g_bsum[blockIdx.x] = s[SCAN_B - 1];
}
__global__ void k_scan2() {
    __shared__ int s[NBLK];
    __shared__ int so[NBLK + 1];
    int t = threadIdx.x;
    if (t < NBLK) s[t] = g_bsum[t];
    __syncthreads();
    if (t == 0) {
        int acc = 0;
        for (int b = 0; b < NBLK; b++) { so[b] = acc; acc += s[b]; }
        so[NBLK] = acc;
    }
    __syncthreads();
    if (t < NBLK) g_bsum2[t] = so[t];
    if (t == 0) g_offs[N_NODES] = so[NBLK];
}
__global__ void k_scan3() {
    int i = blockIdx.x * blockDim.x + threadIdx.x;
    if (i >= N_NODES) return;
    int o = g_offs[i] + g_bsum2[i / SCAN_B];
    g_offs[i]   = o;
    g_cursor[i] = o;
}
__global__ void k_fill(const int* __restrict__ ei) {
    int e = blockIdx.x * blockDim.x + threadIdx.x;
    if (e >= N_EDGES) return;
    int r = ei[e];
    int c = ei[N_EDGES + e];
    int pos = atomicAdd(&g_cursor[c], 1);
    float w = (1.0f - ALPHA) * g_dinv[r] * g_dinv[c];
    g_csr[pos] = make_int2(r * 5, __float_as_int(w));   // uint4-row index
}
__global__ void k_w1t(const float* __restrict__ W1) {
    int i = blockIdx.x * blockDim.x + threadIdx.x;
    if (i >= F_IN * F_H) return;
    int k = i >> 7, n = i & 127;
    float v  = W1[i];
    float hi = tf32_rna(v);
    g_W1T_hi[(size_t)n * F_IN + k] = hi;
    g_W1T_lo[(size_t)n * F_IN + k] = tf32_rna(v - hi);
}

// ---------------- GEMM1 via mma.sync tf32x3 ---------------------------------
#define GST    36
#define GARR   (128 * GST)
#define GSMEM  (4 * GARR * 4)

__global__ void __launch_bounds__(256) k_gemm1_mma(const float* __restrict__ x,
                                                   const float* __restrict__ b1) {
    extern __shared__ float sm[];
    float* xs_h = sm;
    float* xs_l = sm + GARR;
    float* ws_h = sm + 2 * GARR;
    float* ws_l = sm + 3 * GARR;
    uint32_t ws_h32 = smem_u32(ws_h);
    uint32_t ws_l32 = smem_u32(ws_l);

    int tid  = threadIdx.x;
    int wid  = tid >> 5, lid = tid & 31;
    int gid  = lid >> 2, tig = lid & 3;
    int wm   = wid & 3, wn = wid >> 2;
    int row0 = blockIdx.x * 128;

    float acc[2][8][4];
#pragma unroll
    for (int mt = 0; mt < 2; mt++)
#pragma unroll
        for (int nt = 0; nt < 8; nt++)
#pragma unroll
            for (int i = 0; i < 4; i++) acc[mt][nt][i] = 0.0f;

    for (int kt = 0; kt < 16; kt++) {
#pragma unroll
        for (int i = 0; i < 4; i++) {
            int slot = tid + i * 256;
            int n  = slot >> 3;
            int c4 = slot & 7;
            const float* src = &g_W1T_hi[(size_t)n * F_IN + kt * 32 + c4 * 4];
            cp16(ws_h32 + (n * GST + c4 * 4) * 4, src);
            cp16(ws_l32 + (n * GST + c4 * 4) * 4, src + (size_t)F_H * F_IN);
        }
        asm volatile("cp.async.commit_group;" ::: "memory");
#pragma unroll
        for (int i = 0; i < 4; i++) {
            int slot = tid + i * 256;
            int m  = slot >> 3;
            int c4 = slot & 7;
            int grow = row0 + m; if (grow >= N_NODES) grow = N_NODES - 1;
            float4 v = *(const float4*)&x[(size_t)grow * F_IN + kt * 32 + c4 * 4];
            float4 h, l;
            h.x = tf32_rna(v.x); l.x = tf32_rna(v.x - h.x);
            h.y = tf32_rna(v.y); l.y = tf32_rna(v.y - h.y);
            h.z = tf32_rna(v.z); l.z = tf32_rna(v.z - h.z);
            h.w = tf32_rna(v.w); l.w = tf32_rna(v.w - h.w);
            *(float4*)&xs_h[m * GST + c4 * 4] = h;
            *(float4*)&xs_l[m * GST + c4 * 4] = l;
        }
        asm volatile("cp.async.wait_group 0;" ::: "memory");
        __syncthreads();

#pragma unroll
        for (int ks = 0; ks < 4; ks++) {
            int kk = ks * 8;
            float ah[2][4], al[2][4];
#pragma unroll
            for (int mt = 0; mt < 2; mt++) {
                int m = wm * 32 + mt * 16 + gid;
                ah[mt][0] = xs_h[m * GST + kk + tig];
                ah[mt][1] = xs_h[(m + 8) * GST + kk + tig];
                ah[mt][2] = xs_h[m * GST + kk + tig + 4];
                ah[mt][3] = xs_h[(m + 8) * GST + kk + tig + 4];
                al[mt][0] = xs_l[m * GST + kk + tig];
                al[mt][1] = xs_l[(m + 8) * GST + kk + tig];
                al[mt][2] = xs_l[m * GST + kk + tig + 4];
                al[mt][3] = xs_l[(m + 8) * GST + kk + tig + 4];
            }
#pragma unroll
            for (int nt = 0; nt < 8; nt++) {
                int n = wn * 64 + nt * 8 + gid;
                float bh[2], bl[2];
                bh[0] = ws_h[n * GST + kk + tig];
                bh[1] = ws_h[n * GST + kk + tig + 4];
                bl[0] = ws_l[n * GST + kk + tig];
                bl[1] = ws_l[n * GST + kk + tig + 4];
#pragma unroll
                for (int mt = 0; mt < 2; mt++) {
                    mma_tf32(acc[mt][nt], ah[mt], bh);
                    mma_tf32(acc[mt][nt], ah[mt], bl);
                    mma_tf32(acc[mt][nt], al[mt], bh);
                }
            }
        }
        __syncthreads();
    }

#pragma unroll
    for (int nt = 0; nt < 8; nt++) {
        int col = wn * 64 + nt * 8 + tig * 2;
        float2 bb = *(const float2*)&b1[col];
#pragma unroll
        for (int mt = 0; mt < 2; mt++) {
            int r0 = row0 + wm * 32 + mt * 16 + gid;
            if (r0 < N_NODES) {
                float2 o;
                o.x = acc[mt][nt][0] + bb.x;  o.y = acc[mt][nt][1] + bb.y;
                o.x = o.x > 0.f ? o.x : 0.f;  o.y = o.y > 0.f ? o.y : 0.f;
                *(float2*)&g_h1[(size_t)r0 * F_H + col] = o;
            }
            if (r0 + 8 < N_NODES) {
                float2 o;
                o.x = acc[mt][nt][2] + bb.x;  o.y = acc[mt][nt][3] + bb.y;
                o.x = o.x > 0.f ? o.x : 0.f;  o.y = o.y > 0.f ? o.y : 0.f;
                *(float2*)&g_h1[(size_t)(r0 + 8) * F_H + col] = o;
            }
        }
    }
}

// ---------------- GEMM2: h0h = fp16(relu(h1 @ W2 + b2)) ---------------------
__global__ void __launch_bounds__(320) k_gemm2(const float* __restrict__ W2,
                                               const float* __restrict__ b2) {
    __shared__ float hs[64][128];
    int tid  = threadIdx.x;
    int col  = tid % 40;
    int rg   = tid / 40;
    int row0 = blockIdx.x * 64;

    for (int q = tid; q < 2048; q += 320) {
        int r  = q >> 5;
        int c4 = q & 31;
        float4 v = make_float4(0.f, 0.f, 0.f, 0.f);
        if (row0 + r < N_NODES)
            v = *(const float4*)&g_h1[(size_t)(row0 + r) * F_H + c4 * 4];
        *(float4*)&hs[r][c4 * 4] = v;
    }
    __syncthreads();

    float acc[8];
#pragma unroll
    for (int r = 0; r < 8; r++) acc[r] = 0.0f;
#pragma unroll 4
    for (int k = 0; k < 128; k++) {
        float w = W2[(size_t)k * F_OUT + col];
#pragma unroll
        for (int r = 0; r < 8; r++)
            acc[r] = fmaf(hs[rg + 8 * r][k], w, acc[r]);
    }
    float bb = b2[col];
#pragma unroll
    for (int r = 0; r < 8; r++) {
        int row = row0 + rg + 8 * r;
        if (row < N_NODES) {
            float v = acc[r] + bb;
            v = v > 0.0f ? v : 0.0f;
            g_h0h[(size_t)row * F_OUT + col] = __float2half_rn(v);
        }
    }
}

// ---------------- propagation: pull-mode CSR, fp16 z, smem-staged edges -----
// 64 nodes/block x 5 threads/node; thread q owns 8 features (one uint4 of halves).
#define PTILE 2048
template <bool LAST>
__global__ void __launch_bounds__(320) k_pull_h(const __half* __restrict__ srcp,
                                                void* __restrict__ dstv) {
    __shared__ int2 se[PTILE];
    int tid  = threadIdx.x;
    int g    = tid / 5;
    int q    = tid % 5;
    int node = blockIdx.x * 64 + g;
    int nc   = node < N_NODES ? node : N_NODES - 1;

    const uint4* s4 = (const uint4*)srcp;
    const uint4* h4 = (const uint4*)g_h0h;

    float sc = g_selfc[nc];
    uint4 hraw = h4[nc * 5 + q];
    uint4 sraw = s4[nc * 5 + q];
    const __half2* hh = (const __half2*)&hraw;
    const __half2* sh = (const __half2*)&sraw;
    float2 acc[4];
#pragma unroll
    for (int j = 0; j < 4; j++) {
        float2 hv = __half22float2(hh[j]);
        float2 sv = __half22float2(sh[j]);
        acc[j].x = fmaf(sc, sv.x, ALPHA * hv.x);
        acc[j].y = fmaf(sc, sv.y, ALPHA * hv.y);
    }

    int nb0  = blockIdx.x * 64;
    int nb1  = nb0 + 64; if (nb1 > N_NODES) nb1 = N_NODES;
    int base   = g_offs[nb0];
    int endAll = g_offs[nb1];
    int e0 = g_offs[node < N_NODES ? node : N_NODES];
    int e1 = g_offs[node + 1 < N_NODES ? node + 1 : N_NODES];

    for (int t0 = base; t0 < endAll; t0 += PTILE) {
        int cnt = min(PTILE, endAll - t0);
        __syncthreads();
        for (int i = tid; i < cnt; i += 320) se[i] = g_csr[t0 + i];
        __syncthreads();
        int eb = max(e0, t0) - t0;
        int ee = min(e1, t0 + cnt) - t0;
        int e = eb;
        for (; e + 2 <= ee; e += 2) {
            int2 p0 = se[e], p1 = se[e + 1];
            uint4 r0 = __ldg(&s4[p0.x + q]);
            uint4 r1 = __ldg(&s4[p1.x + q]);
            float w0 = __int_as_float(p0.y), w1 = __int_as_float(p1.y);
            const __half2* a0 = (const __half2*)&r0;
            const __half2* a1 = (const __half2*)&r1;
#pragma unroll
            for (int j = 0; j < 4; j++) {
                float2 v0 = __half22float2(a0[j]);
                float2 v1 = __half22float2(a1[j]);
                acc[j].x = fmaf(w0, v0.x, acc[j].x);
                acc[j].y = fmaf(w0, v0.y, acc[j].y);
                acc[j].x = fmaf(w1, v1.x, acc[j].x);
                acc[j].y = fmaf(w1, v1.y, acc[j].y);
            }
        }
        if (e < ee) {
            int2 p = se[e];
            uint4 r = __ldg(&s4[p.x + q]);
            float w = __int_as_float(p.y);
            const __half2* a = (const __half2*)&r;
#pragma unroll
            for (int j = 0; j < 4; j++) {
                float2 v = __half22float2(a[j]);
                acc[j].x = fmaf(w, v.x, acc[j].x);
                acc[j].y = fmaf(w, v.y, acc[j].y);
            }
        }
    }

    if (node < N_NODES) {
        if (LAST) {
            float* out = (float*)dstv;
            float4 o0 = make_float4(acc[0].x, acc[0].y, acc[1].x, acc[1].y);
            float4 o1 = make_float4(acc[2].x, acc[2].y, acc[3].x, acc[3].y);
            *(float4*)&out[(size_t)node * F_OUT + q * 8]     = o0;
            *(float4*)&out[(size_t)node * F_OUT + q * 8 + 4] = o1;
        } else {
            uint4 o;
            __half2* oh = (__half2*)&o;
#pragma unroll
            for (int j = 0; j < 4; j++) oh[j] = __float22half2_rn(acc[j]);
            ((uint4*)dstv)[node * 5 + q] = o;
        }
    }
}

// ---------------- launcher ---------------------------------------------------
extern "C" void kernel_launch(void* const* d_in, const int* in_sizes, int n_in,
                              void* d_out, int out_size) {
    const float* x  = (const float*)d_in[0];
    const int*   ei = (const int*)  d_in[1];
    const float* W1 = (const float*)d_in[2];
    const float* b1 = (const float*)d_in[3];
    const float* W2 = (const float*)d_in[4];
    const float* b2 = (const float*)d_in[5];

    __half *zA, *zB, *h0h;
    cudaGetSymbolAddress((void**)&zA,  g_zhA);
    cudaGetSymbolAddress((void**)&zB,  g_zhB);
    cudaGetSymbolAddress((void**)&h0h, g_h0h);

    cudaFuncSetAttribute(k_gemm1_mma, cudaFuncAttributeMaxDynamicSharedMemorySize, GSMEM);

    // CSR build
    k_zero <<<(N_NODES + 255) / 256, 256>>>();
    k_count<<<(N_EDGES + 255) / 256, 256>>>(ei);
    k_dinv <<<(N_NODES + 255) / 256, 256>>>();
    k_scan1<<<NBLK, SCAN_B>>>();
    k_scan2<<<1, 256>>>();
    k_scan3<<<(N_NODES + 255) / 256, 256>>>();
    k_fill <<<(N_EDGES + 255) / 256, 256>>>(ei);

    // MLP encoder
    k_w1t<<<(F_IN * F_H + 255) / 256, 256>>>(W1);
    k_gemm1_mma<<<(N_NODES + 127) / 128, 256, GSMEM>>>(x, b1);
    k_gemm2<<<(N_NODES + 63) / 64, 320>>>(W2, b2);

    // APPNP propagation (pull mode, fp16 z)
    int pgrid = (N_NODES + 63) / 64;
    const __half* src = h0h;
    for (int it = 0; it < K_ITERS - 1; it++) {
        __half* dst = (it & 1) ? zB : zA;
        k_pull_h<false><<<pgrid, 320>>>(src, dst);
        src = dst;
    }
    k_pull_h<true><<<pgrid, 320>>>(src, d_out);
}

// round 7
// speedup vs baseline: 4.1280x; 1.0752x over previous
#include <cuda_runtime.h>
#include <cuda_fp16.h>
#include <cstdint>

#define N_NODES 100000
#define N_EDGES 3200000
#define F_IN    512
#define F_H     128
#define F_OUT   40
#define K_ITERS 20
#define ALPHA   0.1f

#define SCAN_B  512
#define NBLK    ((N_NODES + SCAN_B - 1) / SCAN_B)   // 196

// ---------------- scratch (device globals; no runtime allocation) ----------
__device__ __half g_h1[(size_t)N_NODES * F_H];     // 25.6 MB (fp16 h1)
__device__ __half g_W1h[(size_t)F_H * F_IN];       // [n][k] hi
__device__ __half g_W1l[(size_t)F_H * F_IN];       // [n][k] lo
__device__ __half g_W2Th[(size_t)F_OUT * F_H];     // [n][k] hi
__device__ __half g_W2Tl[(size_t)F_OUT * F_H];     // [n][k] lo
__device__ __half g_h0h[(size_t)N_NODES * F_OUT];  // 8 MB
__device__ __half g_zhA[(size_t)N_NODES * F_OUT];
__device__ __half g_zhB[(size_t)N_NODES * F_OUT];
__device__ int    g_cnt[N_NODES];
__device__ int    g_offs[N_NODES + 1];
__device__ int    g_cursor[N_NODES];
__device__ int    g_bsum[NBLK];
__device__ int    g_bsum2[NBLK];
__device__ float  g_dinv[N_NODES];
__device__ float  g_selfc[N_NODES];
__device__ int2   g_csr[N_EDGES];                  // {src_row*5 (uint4 units), float_bits(w)}

// ---------------- helpers ----------------------------------------------------
__device__ __forceinline__ void cp16(uint32_t s, const void* g) {
    asm volatile("cp.async.cg.shared.global [%0], [%1], 16;" :: "r"(s), "l"(g));
}
__device__ __forceinline__ uint32_t smem_u32(const void* p) {
    uint32_t a;
    asm("{ .reg .u64 t; cvta.to.shared.u64 t, %1; cvt.u32.u64 %0, t; }" : "=r"(a) : "l"(p));
    return a;
}
__device__ __forceinline__ void mma_f16(float* c, const uint32_t* a, const uint32_t* b) {
    asm volatile(
        "mma.sync.aligned.m16n8k16.row.col.f32.f16.f16.f32 "
        "{%0,%1,%2,%3}, {%4,%5,%6,%7}, {%8,%9}, {%0,%1,%2,%3};"
        : "+f"(c[0]), "+f"(c[1]), "+f"(c[2]), "+f"(c[3])
        : "r"(a[0]), "r"(a[1]), "r"(a[2]), "r"(a[3]), "r"(b[0]), "r"(b[1]));
}

// ---------------- prep: zero cnt + split W1 (to [n][k] hi/lo) + split W2T ---
__global__ void k_prep0(const float* __restrict__ W1, const float* __restrict__ W2) {
    int i = blockIdx.x * blockDim.x + threadIdx.x;
    if (i < F_IN * F_H) {                   // W1 linear: i = k*128+n
        int k = i >> 7, n = i & 127;
        float v = W1[i];
        __half h = __float2half_rn(v);
        g_W1h[(size_t)n * F_IN + k] = h;
        g_W1l[(size_t)n * F_IN + k] = __float2half_rn(v - __half2float(h));
    }
    if (i < F_H * F_OUT) {                  // W2 linear: i = k*40+n
        int k = i / F_OUT, n = i % F_OUT;
        float v = W2[i];
        __half h = __float2half_rn(v);
        g_W2Th[(size_t)n * F_H + k] = h;
        g_W2Tl[(size_t)n * F_H + k] = __float2half_rn(v - __half2float(h));
    }
    if (i < N_NODES) g_cnt[i] = 0;
}

__global__ void k_count(const int* __restrict__ ei) {
    int e = blockIdx.x * blockDim.x + threadIdx.x;
    if (e < N_EDGES) atomicAdd(&g_cnt[ei[N_EDGES + e]], 1);
}
__global__ void k_scan1() {                 // also computes dinv/selfc
    __shared__ int s[SCAN_B];
    int i = blockIdx.x * SCAN_B + threadIdx.x;
    int v = (i < N_NODES) ? g_cnt[i] : 0;
    if (i < N_NODES) {
        float d = (float)(v + 1);
        float r = rsqrtf(d);
        g_dinv[i]  = r;
        g_selfc[i] = (1.0f - ALPHA) * r * r;
    }
    s[threadIdx.x] = v;
    __syncthreads();
#pragma unroll
    for (int off = 1; off < SCAN_B; off <<= 1) {
        int t = (threadIdx.x >= off) ? s[threadIdx.x - off] : 0;
        __syncthreads();
        s[threadIdx.x] += t;
        __syncthreads();
    }
    if (i < N_NODES) g_offs[i] = s[threadIdx.x] - v;
    if (threadIdx.x == SCAN_B - 1) g_bsum[blockIdx.x] = s[SCAN_B - 1];
}
__global__ void k_scan2() {
    __shared__ int s[NBLK];
    __shared__ int so[NBLK + 1];
    int t = threadIdx.x;
    if (t < NBLK) s[t] = g_bsum[t];
    __syncthreads();
    if (t == 0) {
        int acc = 0;
        for (int b = 0; b < NBLK; b++) { so[b] = acc; acc += s[b]; }
        so[NBLK] = acc;
    }
    __syncthreads();
    if (t < NBLK) g_bsum2[t] = so[t];
    if (t == 0) g_offs[N_NODES] = so[NBLK];
}
__global__ void k_scan3() {
    int i = blockIdx.x * blockDim.x + threadIdx.x;
    if (i >= N_NODES) return;
    int o = g_offs[i] + g_bsum2[i / SCAN_B];
    g_offs[i]   = o;
    g_cursor[i] = o;
}
__global__ void k_fill(const int* __restrict__ ei) {
    int e = blockIdx.x * blockDim.x + threadIdx.x;
    if (e >= N_EDGES) return;
    int r = ei[e];
    int c = ei[N_EDGES + e];
    int pos = atomicAdd(&g_cursor[c], 1);
    float w = (1.0f - ALPHA) * g_dinv[r] * g_dinv[c];
    g_csr[pos] = make_int2(r * 5, __float_as_int(w));
}

// ---------------- GEMM1: h1 = fp16(relu(x @ W1 + b1)), fp16x3 MMA -----------
// block 128x128 out, K-tile 32, 8 warps (4m x 2n), m16n8k16.
#define G1ST 40                                      // smem row stride (halves)
__global__ void __launch_bounds__(256) k_gemm1(const float* __restrict__ x,
                                               const float* __restrict__ b1) {
    __shared__ __half xs_h[128 * G1ST], xs_l[128 * G1ST];
    __shared__ __half ws_h[128 * G1ST], ws_l[128 * G1ST];
    uint32_t wsh32 = smem_u32(ws_h), wsl32 = smem_u32(ws_l);

    int tid = threadIdx.x;
    int wid = tid >> 5, lid = tid & 31;
    int g = lid >> 2, tig = lid & 3;
    int wm = wid & 3, wn = wid >> 2;
    int row0 = blockIdx.x * 128;

    float acc[2][8][4];
#pragma unroll
    for (int mt = 0; mt < 2; mt++)
#pragma unroll
        for (int nt = 0; nt < 8; nt++)
#pragma unroll
            for (int i = 0; i < 4; i++) acc[mt][nt][i] = 0.0f;

    for (int kt = 0; kt < 16; kt++) {
        // W tiles via cp.async (pre-split fp16 hi/lo, [n][k])
#pragma unroll
        for (int i = 0; i < 2; i++) {
            int slot = tid + i * 256;                // 0..511
            int n = slot >> 2, c = slot & 3;
            cp16(wsh32 + (n * G1ST + c * 8) * 2, &g_W1h[(size_t)n * F_IN + kt * 32 + c * 8]);
            cp16(wsl32 + (n * G1ST + c * 8) * 2, &g_W1l[(size_t)n * F_IN + kt * 32 + c * 8]);
        }
        asm volatile("cp.async.commit_group;" ::: "memory");
        // x tile: LDG fp32 -> fp16 hi/lo split -> STS
#pragma unroll
        for (int i = 0; i < 4; i++) {
            int slot = tid + i * 256;                // 0..1023
            int m = slot >> 3, c4 = slot & 7;
            int grow = row0 + m; if (grow >= N_NODES) grow = N_NODES - 1;
            float4 v = *(const float4*)&x[(size_t)grow * F_IN + kt * 32 + c4 * 4];
            __half hx0 = __float2half_rn(v.x), hx1 = __float2half_rn(v.y);
            __half hx2 = __float2half_rn(v.z), hx3 = __float2half_rn(v.w);
            __half lx0 = __float2half_rn(v.x - __half2float(hx0));
            __half lx1 = __float2half_rn(v.y - __half2float(hx1));
            __half lx2 = __float2half_rn(v.z - __half2float(hx2));
            __half lx3 = __float2half_rn(v.w - __half2float(hx3));
            __half* ph = &xs_h[m * G1ST + c4 * 4];
            __half* pl = &xs_l[m * G1ST + c4 * 4];
            *(__half2*)ph       = __halves2half2(hx0, hx1);
            *(__half2*)(ph + 2) = __halves2half2(hx2, hx3);
            *(__half2*)pl       = __halves2half2(lx0, lx1);
            *(__half2*)(pl + 2) = __halves2half2(lx2, lx3);
        }
        asm volatile("cp.async.wait_group 0;" ::: "memory");
        __syncthreads();

#pragma unroll
        for (int ks = 0; ks < 2; ks++) {
            int kk = ks * 16;
            uint32_t ah[2][4], al[2][4];
#pragma unroll
            for (int mt = 0; mt < 2; mt++) {
                int m = wm * 32 + mt * 16 + g;
                ah[mt][0] = *(uint32_t*)&xs_h[m * G1ST + kk + 2 * tig];
                ah[mt][1] = *(uint32_t*)&xs_h[(m + 8) * G1ST + kk + 2 * tig];
                ah[mt][2] = *(uint32_t*)&xs_h[m * G1ST + kk + 8 + 2 * tig];
                ah[mt][3] = *(uint32_t*)&xs_h[(m + 8) * G1ST + kk + 8 + 2 * tig];
                al[mt][0] = *(uint32_t*)&xs_l[m * G1ST + kk + 2 * tig];
                al[mt][1] = *(uint32_t*)&xs_l[(m + 8) * G1ST + kk + 2 * tig];
                al[mt][2] = *(uint32_t*)&xs_l[m * G1ST + kk + 8 + 2 * tig];
                al[mt][3] = *(uint32_t*)&xs_l[(m + 8) * G1ST + kk + 8 + 2 * tig];
            }
#pragma unroll
            for (int nt = 0; nt < 8; nt++) {
                int n = wn * 64 + nt * 8 + g;
                uint32_t bh[2], bl[2];
                bh[0] = *(uint32_t*)&ws_h[n * G1ST + kk + 2 * tig];
                bh[1] = *(uint32_t*)&ws_h[n * G1ST + kk + 8 + 2 * tig];
                bl[0] = *(uint32_t*)&ws_l[n * G1ST + kk + 2 * tig];
                bl[1] = *(uint32_t*)&ws_l[n * G1ST + kk + 8 + 2 * tig];
#pragma unroll
                for (int mt = 0; mt < 2; mt++) {
                    mma_f16(acc[mt][nt], ah[mt], bh);
                    mma_f16(acc[mt][nt], ah[mt], bl);
                    mma_f16(acc[mt][nt], al[mt], bh);
                }
            }
        }
        __syncthreads();
    }

    // epilogue: bias + relu -> fp16 h1
#pragma unroll
    for (int nt = 0; nt < 8; nt++) {
        int col = wn * 64 + nt * 8 + tig * 2;
        float2 bb = *(const float2*)&b1[col];
#pragma unroll
        for (int mt = 0; mt < 2; mt++) {
            int r0 = row0 + wm * 32 + mt * 16 + g;
            if (r0 < N_NODES) {
                float ox = acc[mt][nt][0] + bb.x, oy = acc[mt][nt][1] + bb.y;
                ox = ox > 0.f ? ox : 0.f;  oy = oy > 0.f ? oy : 0.f;
                *(__half2*)&g_h1[(size_t)r0 * F_H + col] = __floats2half2_rn(ox, oy);
            }
            if (r0 + 8 < N_NODES) {
                float ox = acc[mt][nt][2] + bb.x, oy = acc[mt][nt][3] + bb.y;
                ox = ox > 0.f ? ox : 0.f;  oy = oy > 0.f ? oy : 0.f;
                *(__half2*)&g_h1[(size_t)(r0 + 8) * F_H + col] = __floats2half2_rn(ox, oy);
            }
        }
    }
}

// ---------------- GEMM2: h0h = fp16(relu(h1 @ W2 + b2)), fp16 MMA -----------
// block 128 rows x 40 cols; 8 warps each own one m16 tile; K=128 (8 k16 steps).
#define G2ST 136
#define G2SMEM ((128 * G2ST + 2 * F_OUT * G2ST) * 2)
__global__ void __launch_bounds__(256) k_gemm2(const float* __restrict__ b2) {
    extern __shared__ __half sm2[];
    __half* hs = sm2;
    __half* wh = sm2 + 128 * G2ST;
    __half* wl = wh + F_OUT * G2ST;
    uint32_t hs32 = smem_u32(hs), wh32 = smem_u32(wh), wl32 = smem_u32(wl);

    int tid = threadIdx.x;
    int wid = tid >> 5, lid = tid & 31;
    int g = lid >> 2, tig = lid & 3;
    int row0 = blockIdx.x * 128;

    // load h1 tile (128 x 128 halves) via cp.async
#pragma unroll
    for (int i = 0; i < 8; i++) {
        int slot = tid + i * 256;                    // 0..2047
        int m = slot >> 4, c = slot & 15;
        int grow = row0 + m; if (grow >= N_NODES) grow = N_NODES - 1;
        cp16(hs32 + (m * G2ST + c * 8) * 2, &g_h1[(size_t)grow * F_H + c * 8]);
    }
    // load W2T tiles (40 x 128 halves, hi+lo)
#pragma unroll
    for (int i = 0; i < 3; i++) {
        int slot = tid + i * 256;
        if (slot < F_OUT * 16) {
            int n = slot >> 4, c = slot & 15;
            cp16(wh32 + (n * G2ST + c * 8) * 2, &g_W2Th[(size_t)n * F_H + c * 8]);
            cp16(wl32 + (n * G2ST + c * 8) * 2, &g_W2Tl[(size_t)n * F_H + c * 8]);
        }
    }
    asm volatile("cp.async.commit_group;" ::: "memory");
    asm volatile("cp.async.wait_group 0;" ::: "memory");
    __syncthreads();

    float acc[5][4];
#pragma unroll
    for (int nt = 0; nt < 5; nt++)
#pragma unroll
        for (int i = 0; i < 4; i++) acc[nt][i] = 0.0f;

#pragma unroll
    for (int ks = 0; ks < 8; ks++) {
        int kk = ks * 16;
        int m = wid * 16 + g;
        uint32_t a[4];
        a[0] = *(uint32_t*)&hs[m * G2ST + kk + 2 * tig];
        a[1] = *(uint32_t*)&hs[(m + 8) * G2ST + kk + 2 * tig];
        a[2] = *(uint32_t*)&hs[m * G2ST + kk + 8 + 2 * tig];
        a[3] = *(uint32_t*)&hs[(m + 8) * G2ST + kk + 8 + 2 * tig];
#pragma unroll
        for (int nt = 0; nt < 5; nt++) {
            int n = nt * 8 + g;
            uint32_t bhv[2], blv[2];
            bhv[0] = *(uint32_t*)&wh[n * G2ST + kk + 2 * tig];
            bhv[1] = *(uint32_t*)&wh[n * G2ST + kk + 8 + 2 * tig];
            blv[0] = *(uint32_t*)&wl[n * G2ST + kk + 2 * tig];
            blv[1] = *(uint32_t*)&wl[n * G2ST + kk + 8 + 2 * tig];
            mma_f16(acc[nt], a, bhv);
            mma_f16(acc[nt], a, blv);
        }
    }

#pragma unroll
    for (int nt = 0; nt < 5; nt++) {
        int col = nt * 8 + tig * 2;
        float2 bb = *(const float2*)&b2[col];
        int r0 = row0 + wid * 16 + g;
        if (r0 < N_NODES) {
            float ox = acc[nt][0] + bb.x, oy = acc[nt][1] + bb.y;
            ox = ox > 0.f ? ox : 0.f;  oy = oy > 0.f ? oy : 0.f;
            *(__half2*)&g_h0h[(size_t)r0 * F_OUT + col] = __floats2half2_rn(ox, oy);
        }
        if (r0 + 8 < N_NODES) {
            float ox = acc[nt][2] + bb.x, oy = acc[nt][3] + bb.y;
            ox = ox > 0.f ? ox : 0.f;  oy = oy > 0.f ? oy : 0.f;
            *(__half2*)&g_h0h[(size_t)(r0 + 8) * F_OUT + col] = __floats2half2_rn(ox, oy);
        }
    }
}

// ---------------- propagation: pull-mode CSR, fp16 z, unroll 4 --------------
#define PTILE 2048
template <bool LAST>
__global__ void __launch_bounds__(320) k_pull_h(const __half* __restrict__ srcp,
                                                void* __restrict__ dstv) {
    __shared__ int2 se[PTILE];
    int tid  = threadIdx.x;
    int g    = tid / 5;
    int q    = tid % 5;
    int node = blockIdx.x * 64 + g;
    int nc   = node < N_NODES ? node : N_NODES - 1;

    const uint4* s4 = (const uint4*)srcp;
    const uint4* h4 = (const uint4*)g_h0h;

    float sc = g_selfc[nc];
    uint4 hraw = h4[nc * 5 + q];
    uint4 sraw = s4[nc * 5 + q];
    const __half2* hh = (const __half2*)&hraw;
    const __half2* sh = (const __half2*)&sraw;
    float2 acc[4];
#pragma unroll
    for (int j = 0; j < 4; j++) {
        float2 hv = __half22float2(hh[j]);
        float2 sv = __half22float2(sh[j]);
        acc[j].x = fmaf(sc, sv.x, ALPHA * hv.x);
        acc[j].y = fmaf(sc, sv.y, ALPHA * hv.y);
    }

    int nb0  = blockIdx.x * 64;
    int nb1  = nb0 + 64; if (nb1 > N_NODES) nb1 = N_NODES;
    int base   = g_offs[nb0];
    int endAll = g_offs[nb1];
    int e0 = g_offs[node < N_NODES ? node : N_NODES];
    int e1 = g_offs[node + 1 < N_NODES ? node + 1 : N_NODES];

    for (int t0 = base; t0 < endAll; t0 += PTILE) {
        int cnt = min(PTILE, endAll - t0);
        __syncthreads();
        for (int i = tid; i < cnt; i += 320) se[i] = g_csr[t0 + i];
        __syncthreads();
        int eb = max(e0, t0) - t0;
        int ee = min(e1, t0 + cnt) - t0;
        int e = eb;
        for (; e + 4 <= ee; e += 4) {
            int2 p0 = se[e], p1 = se[e + 1], p2 = se[e + 2], p3 = se[e + 3];
            uint4 r0 = __ldg(&s4[p0.x + q]);
            uint4 r1 = __ldg(&s4[p1.x + q]);
            uint4 r2 = __ldg(&s4[p2.x + q]);
            uint4 r3 = __ldg(&s4[p3.x + q]);
            float w0 = __int_as_float(p0.y), w1 = __int_as_float(p1.y);
            float w2 = __int_as_float(p2.y), w3 = __int_as_float(p3.y);
            const __half2* a0 = (const __half2*)&r0;
            const __half2* a1 = (const __half2*)&r1;
            const __half2* a2 = (const __half2*)&r2;
            const __half2* a3 = (const __half2*)&r3;
#pragma unroll
            for (int j = 0; j < 4; j++) {
                float2 v0 = __half22float2(a0[j]);
                float2 v1 = __half22float2(a1[j]);
                float2 v2 = __half22float2(a2[j]);
                float2 v3 = __half22float2(a3[j]);
                acc[j].x = fmaf(w0, v0.x, acc[j].x); acc[j].y = fmaf(w0, v0.y, acc[j].y);
                acc[j].x = fmaf(w1, v1.x, acc[j].x); acc[j].y = fmaf(w1, v1.y, acc[j].y);
                acc[j].x = fmaf(w2, v2.x, acc[j].x); acc[j].y = fmaf(w2, v2.y, acc[j].y);
                acc[j].x = fmaf(w3, v3.x, acc[j].x); acc[j].y = fmaf(w3, v3.y, acc[j].y);
            }
        }
        for (; e < ee; e++) {
            int2 p = se[e];
            uint4 r = __ldg(&s4[p.x + q]);
            float w = __int_as_float(p.y);
            const __half2* a = (const __half2*)&r;
#pragma unroll
            for (int j = 0; j < 4; j++) {
                float2 v = __half22float2(a[j]);
                acc[j].x = fmaf(w, v.x, acc[j].x);
                acc[j].y = fmaf(w, v.y, acc[j].y);
            }
        }
    }

    if (node < N_NODES) {
        if (LAST) {
            float* out = (float*)dstv;
            float4 o0 = make_float4(acc[0].x, acc[0].y, acc[1].x, acc[1].y);
            float4 o1 = make_float4(acc[2].x, acc[2].y, acc[3].x, acc[3].y);
            *(float4*)&out[(size_t)node * F_OUT + q * 8]     = o0;
            *(float4*)&out[(size_t)node * F_OUT + q * 8 + 4] = o1;
        } else {
            uint4 o;
            __half2* oh = (__half2*)&o;
#pragma unroll
            for (int j = 0; j < 4; j++) oh[j] = __float22half2_rn(acc[j]);
            ((uint4*)dstv)[node * 5 + q] = o;
        }
    }
}

// ---------------- launcher ---------------------------------------------------
extern "C" void kernel_launch(void* const* d_in, const int* in_sizes, int n_in,
                              void* d_out, int out_size) {
    const float* x  = (const float*)d_in[0];
    const int*   ei = (const int*)  d_in[1];
    const float* W1 = (const float*)d_in[2];
    const float* b1 = (const float*)d_in[3];
    const float* W2 = (const float*)d_in[4];
    const float* b2 = (const float*)d_in[5];

    __half *zA, *zB, *h0h;
    cudaGetSymbolAddress((void**)&zA,  g_zhA);
    cudaGetSymbolAddress((void**)&zB,  g_zhB);
    cudaGetSymbolAddress((void**)&h0h, g_h0h);

    cudaFuncSetAttribute(k_gemm2, cudaFuncAttributeMaxDynamicSharedMemorySize, G2SMEM);

    // CSR build + weight prep
    k_prep0<<<(N_NODES + 255) / 256, 256>>>(W1, W2);
    k_count<<<(N_EDGES + 255) / 256, 256>>>(ei);
    k_scan1<<<NBLK, SCAN_B>>>();
    k_scan2<<<1, 256>>>();
    k_scan3<<<(N_NODES + 255) / 256, 256>>>();
    k_fill <<<(N_EDGES + 255) / 256, 256>>>(ei);

    // MLP encoder (fp16 tensor-core MMA)
    k_gemm1<<<(N_NODES + 127) / 128, 256>>>(x, b1);
    k_gemm2<<<(N_NODES + 127) / 128, 256, G2SMEM>>>(b2);

    // APPNP propagation (pull mode, fp16 z)
    int pgrid = (N_NODES + 63) / 64;
    const __half* src = h0h;
    for (int it = 0; it < K_ITERS - 1; it++) {
        __half* dst = (it & 1) ? zB : zA;
        k_pull_h<false><<<pgrid, 320>>>(src, dst);
        src = dst;
    }
    k_pull_h<true><<<pgrid, 320>>>(src, d_out);
}

// round 9
// speedup vs baseline: 4.1328x; 1.0011x over previous
#include <cuda_runtime.h>
#include <cuda_fp16.h>
#include <cstdint>

#define N_NODES 100000
#define N_EDGES 3200000
#define F_IN    512
#define F_H     128
#define F_OUT   40
#define K_ITERS 20
#define ALPHA   0.1f

#define SCAN_B  512
#define NBLK    ((N_NODES + SCAN_B - 1) / SCAN_B)   // 196

// ---------------- scratch (device globals; no runtime allocation) ----------
__device__ __half g_h1[(size_t)N_NODES * F_H];
__device__ __half g_W1h[(size_t)F_H * F_IN];
__device__ __half g_W1l[(size_t)F_H * F_IN];
__device__ __half g_W2Th[(size_t)F_OUT * F_H];
__device__ __half g_W2Tl[(size_t)F_OUT * F_H];
__device__ __half g_h0h[(size_t)N_NODES * F_OUT];
__device__ __half g_zhA[(size_t)N_NODES * F_OUT];
__device__ __half g_zhB[(size_t)N_NODES * F_OUT];
__device__ int    g_cnt[N_NODES];
__device__ int    g_offs[N_NODES + 1];
__device__ int    g_cursor[N_NODES];
__device__ int    g_bsum[NBLK];
__device__ int    g_bsum2[NBLK];
__device__ float  g_dinv[N_NODES];
__device__ float  g_selfc[N_NODES];
__device__ int2   g_csr[N_EDGES];                  // {src_row*5 (uint4 units), float_bits(w)}

// ---------------- helpers ----------------------------------------------------
__device__ __forceinline__ void cp16(uint32_t s, const void* g) {
    asm volatile("cp.async.cg.shared.global [%0], [%1], 16;" :: "r"(s), "l"(g));
}
__device__ __forceinline__ uint32_t smem_u32(const void* p) {
    uint32_t a;
    asm("{ .reg .u64 t; cvta.to.shared.u64 t, %1; cvt.u32.u64 %0, t; }" : "=r"(a) : "l"(p));
    return a;
}
__device__ __forceinline__ void mma_f16(float* c, const uint32_t* a, const uint32_t* b) {
    asm volatile(
        "mma.sync.aligned.m16n8k16.row.col.f32.f16.f16.f32 "
        "{%0,%1,%2,%3}, {%4,%5,%6,%7}, {%8,%9}, {%0,%1,%2,%3};"
        : "+f"(c[0]), "+f"(c[1]), "+f"(c[2]), "+f"(c[3])
        : "r"(a[0]), "r"(a[1]), "r"(a[2]), "r"(a[3]), "r"(b[0]), "r"(b[1]));
}

// ---------------- prep kernels ----------------------------------------------
__global__ void k_prep0(const float* __restrict__ W1, const float* __restrict__ W2) {
    int i = blockIdx.x * blockDim.x + threadIdx.x;
    if (i < F_IN * F_H) {
        int k = i >> 7, n = i & 127;
        float v = W1[i];
        __half h = __float2half_rn(v);
        g_W1h[(size_t)n * F_IN + k] = h;
        g_W1l[(size_t)n * F_IN + k] = __float2half_rn(v - __half2float(h));
    }
    if (i < F_H * F_OUT) {
        int k = i / F_OUT, n = i % F_OUT;
        float v = W2[i];
        __half h = __float2half_rn(v);
        g_W2Th[(size_t)n * F_H + k] = h;
        g_W2Tl[(size_t)n * F_H + k] = __float2half_rn(v - __half2float(h));
    }
    if (i < N_NODES) g_cnt[i] = 0;
}
__global__ void k_count(const int* __restrict__ ei) {
    int e = blockIdx.x * blockDim.x + threadIdx.x;
    if (e < N_EDGES) atomicAdd(&g_cnt[ei[N_EDGES + e]], 1);
}
__global__ void k_scan1() {
    __shared__ int s[SCAN_B];
    int i = blockIdx.x * SCAN_B + threadIdx.x;
    int v = (i < N_NODES) ? g_cnt[i] : 0;
    if (i < N_NODES) {
        float d = (float)(v + 1);
        float r = rsqrtf(d);
        g_dinv[i]  = r;
        g_selfc[i] = (1.0f - ALPHA) * r * r;
    }
    s[threadIdx.x] = v;
    __syncthreads();
#pragma unroll
    for (int off = 1; off < SCAN_B; off <<= 1) {
        int t = (threadIdx.x >= off) ? s[threadIdx.x - off] : 0;
        __syncthreads();
        s[threadIdx.x] += t;
        __syncthreads();
    }
    if (i < N_NODES) g_offs[i] = s[threadIdx.x] - v;
    if (threadIdx.x == SCAN_B - 1) g_bsum[blockIdx.x] = s[SCAN_B - 1];
}
__global__ void k_scan2() {                 // parallel Hillis-Steele over NBLK<=256
    __shared__ int s[256];
    int t = threadIdx.x;
    int v = (t < NBLK) ? g_bsum[t] : 0;
    s[t] = v;
    __syncthreads();
#pragma unroll
    for (int off = 1; off < 256; off <<= 1) {
        int u = (t >= off) ? s[t - off] : 0;
        __syncthreads();
        s[t] += u;
        __syncthreads();
    }
    if (t < NBLK) g_bsum2[t] = s[t] - v;    // exclusive
    if (t == 0) g_offs[N_NODES] = s[255];
}
__global__ void k_scan3() {
    int i = blockIdx.x * blockDim.x + threadIdx.x;
    if (i >= N_NODES) return;
    int o = g_offs[i] + g_bsum2[i / SCAN_B];
    g_offs[i]   = o;
    g_cursor[i] = o;
}
__global__ void k_fill(const int* __restrict__ ei) {
    int e = blockIdx.x * blockDim.x + threadIdx.x;
    if (e >= N_EDGES) return;
    int r = ei[e];
    int c = ei[N_EDGES + e];
    int pos = atomicAdd(&g_cursor[c], 1);
    float w = (1.0f - ALPHA) * g_dinv[r] * g_dinv[c];
    g_csr[pos] = make_int2(r * 5, __float_as_int(w));
}

// ---------------- GEMM1: h1 = fp16(relu(x @ W1 + b1)), fp16x3 MMA -----------
#define G1ST 40
__global__ void __launch_bounds__(256) k_gemm1(const float* __restrict__ x,
                                               const float* __restrict__ b1) {
    __shared__ __half xs_h[128 * G1ST], xs_l[128 * G1ST];
    __shared__ __half ws_h[128 * G1ST], ws_l[128 * G1ST];
    uint32_t wsh32 = smem_u32(ws_h), wsl32 = smem_u32(ws_l);

    int tid = threadIdx.x;
    int wid = tid >> 5, lid = tid & 31;
    int g = lid >> 2, tig = lid & 3;
    int wm = wid & 3, wn = wid >> 2;
    int row0 = blockIdx.x * 128;

    float acc[2][8][4];
#pragma unroll
    for (int mt = 0; mt < 2; mt++)
#pragma unroll
        for (int nt = 0; nt < 8; nt++)
#pragma unroll
            for (int i = 0; i < 4; i++) acc[mt][nt][i] = 0.0f;

    for (int kt = 0; kt < 16; kt++) {
#pragma unroll
        for (int i = 0; i < 2; i++) {
            int slot = tid + i * 256;
            int n = slot >> 2, c = slot & 3;
            cp16(wsh32 + (n * G1ST + c * 8) * 2, &g_W1h[(size_t)n * F_IN + kt * 32 + c * 8]);
            cp16(wsl32 + (n * G1ST + c * 8) * 2, &g_W1l[(size_t)n * F_IN + kt * 32 + c * 8]);
        }
        asm volatile("cp.async.commit_group;" ::: "memory");
#pragma unroll
        for (int i = 0; i < 4; i++) {
            int slot = tid + i * 256;
            int m = slot >> 3, c4 = slot & 7;
            int grow = row0 + m; if (grow >= N_NODES) grow = N_NODES - 1;
            float4 v = *(const float4*)&x[(size_t)grow * F_IN + kt * 32 + c4 * 4];
            __half hx0 = __float2half_rn(v.x), hx1 = __float2half_rn(v.y);
            __half hx2 = __float2half_rn(v.z), hx3 = __float2half_rn(v.w);
            __half lx0 = __float2half_rn(v.x - __half2float(hx0));
            __half lx1 = __float2half_rn(v.y - __half2float(hx1));
            __half lx2 = __float2half_rn(v.z - __half2float(hx2));
            __half lx3 = __float2half_rn(v.w - __half2float(hx3));
            __half* ph = &xs_h[m * G1ST + c4 * 4];
            __half* pl = &xs_l[m * G1ST + c4 * 4];
            *(__half2*)ph       = __halves2half2(hx0, hx1);
            *(__half2*)(ph + 2) = __halves2half2(hx2, hx3);
            *(__half2*)pl       = __halves2half2(lx0, lx1);
            *(__half2*)(pl + 2) = __halves2half2(lx2, lx3);
        }
        asm volatile("cp.async.wait_group 0;" ::: "memory");
        __syncthreads();

#pragma unroll
        for (int ks = 0; ks < 2; ks++) {
            int kk = ks * 16;
            uint32_t ah[2][4], al[2][4];
#pragma unroll
            for (int mt = 0; mt < 2; mt++) {
                int m = wm * 32 + mt * 16 + g;
                ah[mt][0] = *(uint32_t*)&xs_h[m * G1ST + kk + 2 * tig];
                ah[mt][1] = *(uint32_t*)&xs_h[(m + 8) * G1ST + kk + 2 * tig];
                ah[mt][2] = *(uint32_t*)&xs_h[m * G1ST + kk + 8 + 2 * tig];
                ah[mt][3] = *(uint32_t*)&xs_h[(m + 8) * G1ST + kk + 8 + 2 * tig];
                al[mt][0] = *(uint32_t*)&xs_l[m * G1ST + kk + 2 * tig];
                al[mt][1] = *(uint32_t*)&xs_l[(m + 8) * G1ST + kk + 2 * tig];
                al[mt][2] = *(uint32_t*)&xs_l[m * G1ST + kk + 8 + 2 * tig];
                al[mt][3] = *(uint32_t*)&xs_l[(m + 8) * G1ST + kk + 8 + 2 * tig];
            }
#pragma unroll
            for (int nt = 0; nt < 8; nt++) {
                int n = wn * 64 + nt * 8 + g;
                uint32_t bh[2], bl[2];
                bh[0] = *(uint32_t*)&ws_h[n * G1ST + kk + 2 * tig];
                bh[1] = *(uint32_t*)&ws_h[n * G1ST + kk + 8 + 2 * tig];
                bl[0] = *(uint32_t*)&ws_l[n * G1ST + kk + 2 * tig];
                bl[1] = *(uint32_t*)&ws_l[n * G1ST + kk + 8 + 2 * tig];
#pragma unroll
                for (int mt = 0; mt < 2; mt++) {
                    mma_f16(acc[mt][nt], ah[mt], bh);
                    mma_f16(acc[mt][nt], ah[mt], bl);
                    mma_f16(acc[mt][nt], al[mt], bh);
                }
            }
        }
        __syncthreads();
    }

#pragma unroll
    for (int nt = 0; nt < 8; nt++) {
        int col = wn * 64 + nt * 8 + tig * 2;
        float2 bb = *(const float2*)&b1[col];
#pragma unroll
        for (int mt = 0; mt < 2; mt++) {
            int r0 = row0 + wm * 32 + mt * 16 + g;
            if (r0 < N_NODES) {
                float ox = acc[mt][nt][0] + bb.x, oy = acc[mt][nt][1] + bb.y;
                ox = ox > 0.f ? ox : 0.f;  oy = oy > 0.f ? oy : 0.f;
                *(__half2*)&g_h1[(size_t)r0 * F_H + col] = __floats2half2_rn(ox, oy);
            }
            if (r0 + 8 < N_NODES) {
                float ox = acc[mt][nt][2] + bb.x, oy = acc[mt][nt][3] + bb.y;
                ox = ox > 0.f ? ox : 0.f;  oy = oy > 0.f ? oy : 0.f;
                *(__half2*)&g_h1[(size_t)(r0 + 8) * F_H + col] = __floats2half2_rn(ox, oy);
            }
        }
    }
}

// ---------------- GEMM2: h0h = fp16(relu(h1 @ W2 + b2)), fp16 MMA -----------
#define G2ST 136
#define G2SMEM ((128 * G2ST + 2 * F_OUT * G2ST) * 2)
__global__ void __launch_bounds__(256) k_gemm2(const float* __restrict__ b2) {
    extern __shared__ __half sm2[];
    __half* hs = sm2;
    __half* wh = sm2 + 128 * G2ST;
    __half* wl = wh + F_OUT * G2ST;
    uint32_t hs32 = smem_u32(hs), wh32 = smem_u32(wh), wl32 = smem_u32(wl);

    int tid = threadIdx.x;
    int wid = tid >> 5, lid = tid & 31;
    int g = lid >> 2, tig = lid & 3;
    int row0 = blockIdx.x * 128;

#pragma unroll
    for (int i = 0; i < 8; i++) {
        int slot = tid + i * 256;
        int m = slot >> 4, c = slot & 15;
        int grow = row0 + m; if (grow >= N_NODES) grow = N_NODES - 1;
        cp16(hs32 + (m * G2ST + c * 8) * 2, &g_h1[(size_t)grow * F_H + c * 8]);
    }
#pragma unroll
    for (int i = 0; i < 3; i++) {
        int slot = tid + i * 256;
        if (slot < F_OUT * 16) {
            int n = slot >> 4, c = slot & 15;
            cp16(wh32 + (n * G2ST + c * 8) * 2, &g_W2Th[(size_t)n * F_H + c * 8]);
            cp16(wl32 + (n * G2ST + c * 8) * 2, &g_W2Tl[(size_t)n * F_H + c * 8]);
        }
    }
    asm volatile("cp.async.commit_group;" ::: "memory");
    asm volatile("cp.async.wait_group 0;" ::: "memory");
    __syncthreads();

    float acc[5][4];
#pragma unroll
    for (int nt = 0; nt < 5; nt++)
#pragma unroll
        for (int i = 0; i < 4; i++) acc[nt][i] = 0.0f;

#pragma unroll
    for (int ks = 0; ks < 8; ks++) {
        int kk = ks * 16;
        int m = wid * 16 + g;
        uint32_t a[4];
        a[0] = *(uint32_t*)&hs[m * G2ST + kk + 2 * tig];
        a[1] = *(uint32_t*)&hs[(m + 8) * G2ST + kk + 2 * tig];
        a[2] = *(uint32_t*)&hs[m * G2ST + kk + 8 + 2 * tig];
        a[3] = *(uint32_t*)&hs[(m + 8) * G2ST + kk + 8 + 2 * tig];
#pragma unroll
        for (int nt = 0; nt < 5; nt++) {
            int n = nt * 8 + g;
            uint32_t bhv[2], blv[2];
            bhv[0] = *(uint32_t*)&wh[n * G2ST + kk + 2 * tig];
            bhv[1] = *(uint32_t*)&wh[n * G2ST + kk + 8 + 2 * tig];
            blv[0] = *(uint32_t*)&wl[n * G2ST + kk + 2 * tig];
            blv[1] = *(uint32_t*)&wl[n * G2ST + kk + 8 + 2 * tig];
            mma_f16(acc[nt], a, bhv);
            mma_f16(acc[nt], a, blv);
        }
    }

#pragma unroll
    for (int nt = 0; nt < 5; nt++) {
        int col = nt * 8 + tig * 2;
        float2 bb = *(const float2*)&b2[col];
        int r0 = row0 + wid * 16 + g;
        if (r0 < N_NODES) {
            float ox = acc[nt][0] + bb.x, oy = acc[nt][1] + bb.y;
            ox = ox > 0.f ? ox : 0.f;  oy = oy > 0.f ? oy : 0.f;
            *(__half2*)&g_h0h[(size_t)r0 * F_OUT + col] = __floats2half2_rn(ox, oy);
        }
        if (r0 + 8 < N_NODES) {
            float ox = acc[nt][2] + bb.x, oy = acc[nt][3] + bb.y;
            ox = ox > 0.f ? ox : 0.f;  oy = oy > 0.f ? oy : 0.f;
            *(__half2*)&g_h0h[(size_t)(r0 + 8) * F_OUT + col] = __floats2half2_rn(ox, oy);
        }
    }
}

// ---------------- propagation: warp-per-node pull, no block sync ------------
// Warp processes NPW nodes sequentially. 6 groups x 5 lanes split the edge list;
// lane q of each group loads uint4 chunk q of the source row. Cross-group
// reduction via 2 shfl rounds. Lanes 30,31 idle (acc=0, safe shfl sources).
#define NPW 8
template <bool LAST>
__global__ void __launch_bounds__(256) k_pull_w(const __half* __restrict__ srcp,
                                                void* __restrict__ dstv) {
    int lane = threadIdx.x & 31;
    int gw   = blockIdx.x * 8 + (threadIdx.x >> 5);
    int n0 = gw * NPW;
    if (n0 >= N_NODES) return;
    int n1 = n0 + NPW; if (n1 > N_NODES) n1 = N_NODES;

    const uint4* s4 = (const uint4*)srcp;
    const uint4* h4 = (const uint4*)g_h0h;
    int group = lane / 5;
    int q     = lane % 5;
    bool act  = lane < 30;

    for (int n = n0; n < n1; n++) {
        int e0 = g_offs[n], e1 = g_offs[n + 1];
        float2 acc[4];
#pragma unroll
        for (int j = 0; j < 4; j++) acc[j] = make_float2(0.f, 0.f);

        if (act) {
            int e = e0 + group;
            for (; e + 6 < e1; e += 12) {
                int2 p0 = __ldg(&g_csr[e]);
                int2 p1 = __ldg(&g_csr[e + 6]);
                uint4 r0 = __ldg(&s4[p0.x + q]);
                uint4 r1 = __ldg(&s4[p1.x + q]);
                float w0 = __int_as_float(p0.y), w1 = __int_as_float(p1.y);
                const __half2* a0 = (const __half2*)&r0;
                const __half2* a1 = (const __half2*)&r1;
#pragma unroll
                for (int j = 0; j < 4; j++) {
                    float2 v0 = __half22float2(a0[j]);
                    float2 v1 = __half22float2(a1[j]);
                    acc[j].x = fmaf(w0, v0.x, acc[j].x); acc[j].y = fmaf(w0, v0.y, acc[j].y);
                    acc[j].x = fmaf(w1, v1.x, acc[j].x); acc[j].y = fmaf(w1, v1.y, acc[j].y);
                }
            }
            if (e < e1) {
                int2 p = __ldg(&g_csr[e]);
                uint4 r = __ldg(&s4[p.x + q]);
                float w = __int_as_float(p.y);
                const __half2* a = (const __half2*)&r;
#pragma unroll
                for (int j = 0; j < 4; j++) {
                    float2 v = __half22float2(a[j]);
                    acc[j].x = fmaf(w, v.x, acc[j].x);
                    acc[j].y = fmaf(w, v.y, acc[j].y);
                }
            }
        }

        // reduce groups: round1 (+15), then snapshot (+5, +10)
#pragma unroll
        for (int j = 0; j < 4; j++) {
            acc[j].x += __shfl_sync(0xFFFFFFFFu, acc[j].x, (lane + 15) & 31);
            acc[j].y += __shfl_sync(0xFFFFFFFFu, acc[j].y, (lane + 15) & 31);
        }
#pragma unroll
        for (int j = 0; j < 4; j++) {
            float tx1 = __shfl_sync(0xFFFFFFFFu, acc[j].x, (lane + 5) & 31);
            float ty1 = __shfl_sync(0xFFFFFFFFu, acc[j].y, (lane + 5) & 31);
            float tx2 = __shfl_sync(0xFFFFFFFFu, acc[j].x, (lane + 10) & 31);
            float ty2 = __shfl_sync(0xFFFFFFFFu, acc[j].y, (lane + 10) & 31);
            acc[j].x += tx1 + tx2;
            acc[j].y += ty1 + ty2;
        }

        if (lane < 5) {
            float sc = g_selfc[n];
            uint4 hraw = h4[n * 5 + lane];
            uint4 sraw = s4[n * 5 + lane];
            const __half2* hh = (const __half2*)&hraw;
            const __half2* sh = (const __half2*)&sraw;
#pragma unroll
            for (int j = 0; j < 4; j++) {
                float2 hv = __half22float2(hh[j]);
                float2 sv = __half22float2(sh[j]);
                acc[j].x += fmaf(sc, sv.x, ALPHA * hv.x);
                acc[j].y += fmaf(sc, sv.y, ALPHA * hv.y);
            }
            if (LAST) {
                float* out = (float*)dstv;
                float4 o0 = make_float4(acc[0].x, acc[0].y, acc[1].x, acc[1].y);
                float4 o1 = make_float4(acc[2].x, acc[2].y, acc[3].x, acc[3].y);
                *(float4*)&out[(size_t)n * F_OUT + lane * 8]     = o0;
                *(float4*)&out[(size_t)n * F_OUT + lane * 8 + 4] = o1;
            } else {
                uint4 o;
                __half2* oh = (__half2*)&o;
#pragma unroll
                for (int j = 0; j < 4; j++) oh[j] = __float22half2_rn(acc[j]);
                ((uint4*)dstv)[n * 5 + lane] = o;
            }
        }
    }
}

// ---------------- launcher ---------------------------------------------------
extern "C" void kernel_launch(void* const* d_in, const int* in_sizes, int n_in,
                              void* d_out, int out_size) {
    const float* x  = (const float*)d_in[0];
    const int*   ei = (const int*)  d_in[1];
    const float* W1 = (const float*)d_in[2];
    const float* b1 = (const float*)d_in[3];
    const float* W2 = (const float*)d_in[4];
    const float* b2 = (const float*)d_in[5];

    __half *zA, *zB, *h0h;
    cudaGetSymbolAddress((void**)&zA,  g_zhA);
    cudaGetSymbolAddress((void**)&zB,  g_zhB);
    cudaGetSymbolAddress((void**)&h0h, g_h0h);

    cudaFuncSetAttribute(k_gemm2, cudaFuncAttributeMaxDynamicSharedMemorySize, G2SMEM);

    // CSR build + weight prep
    k_prep0<<<(N_NODES + 255) / 256, 256>>>(W1, W2);
    k_count<<<(N_EDGES + 255) / 256, 256>>>(ei);
    k_scan1<<<NBLK, SCAN_B>>>();
    k_scan2<<<1, 256>>>();
    k_scan3<<<(N_NODES + 255) / 256, 256>>>();
    k_fill <<<(N_EDGES + 255) / 256, 256>>>(ei);

    // MLP encoder (fp16 tensor-core MMA)
    k_gemm1<<<(N_NODES + 127) / 128, 256>>>(x, b1);
    k_gemm2<<<(N_NODES + 127) / 128, 256, G2SMEM>>>(b2);

    // APPNP propagation (warp-per-node pull, fp16 z)
    int nwarps = (N_NODES + NPW - 1) / NPW;
    int pgrid  = (nwarps + 7) / 8;
    const __half* src = h0h;
    for (int it = 0; it < K_ITERS - 1; it++) {
        __half* dst = (it & 1) ? zB : zA;
        k_pull_w<false><<<pgrid, 256>>>(src, dst);
        src = dst;
    }
    k_pull_w<true><<<pgrid, 256>>>(src, d_out);
}

// round 10
// speedup vs baseline: 4.1989x; 1.0160x over previous
#include <cuda_runtime.h>
#include <cuda_fp16.h>
#include <cstdint>

#define N_NODES 100000
#define N_EDGES 3200000
#define F_IN    512
#define F_H     128
#define F_OUT   40
#define F_PAD   64          // padded row length in halves (128 B rows)
#define K_ITERS 20
#define ALPHA   0.1f

#define SCAN_B  512
#define NBLK    ((N_NODES + SCAN_B - 1) / SCAN_B)   // 196

// ---------------- scratch (device globals; no runtime allocation) ----------
__device__ __half   g_h1[(size_t)N_NODES * F_H];
__device__ __half   g_W1h[(size_t)F_H * F_IN];
__device__ __half   g_W1l[(size_t)F_H * F_IN];
__device__ __half   g_W2Th[(size_t)F_OUT * F_H];
__device__ __half   g_W2Tl[(size_t)F_OUT * F_H];
__device__ __half   g_h0h[(size_t)N_NODES * F_PAD];   // padded 128B rows
__device__ __half   g_zhA[(size_t)N_NODES * F_PAD];
__device__ __half   g_zhB[(size_t)N_NODES * F_PAD];
__device__ int      g_cnt[N_NODES];
__device__ int      g_offs[N_NODES + 1];
__device__ int      g_cursor[N_NODES];
__device__ int      g_bsum[NBLK];
__device__ int      g_bsum2[NBLK];
__device__ float    g_dinv[N_NODES];
__device__ float    g_selfc[N_NODES];
__device__ uint32_t g_csr[N_EDGES];     // idx(17b)<<15 | half_bits(w)&0x7FFF

// ---------------- helpers ----------------------------------------------------
__device__ __forceinline__ void cp16(uint32_t s, const void* g) {
    asm volatile("cp.async.cg.shared.global [%0], [%1], 16;" :: "r"(s), "l"(g));
}
__device__ __forceinline__ uint32_t smem_u32(const void* p) {
    uint32_t a;
    asm("{ .reg .u64 t; cvta.to.shared.u64 t, %1; cvt.u32.u64 %0, t; }" : "=r"(a) : "l"(p));
    return a;
}
__device__ __forceinline__ void mma_f16(float* c, const uint32_t* a, const uint32_t* b) {
    asm volatile(
        "mma.sync.aligned.m16n8k16.row.col.f32.f16.f16.f32 "
        "{%0,%1,%2,%3}, {%4,%5,%6,%7}, {%8,%9}, {%0,%1,%2,%3};"
        : "+f"(c[0]), "+f"(c[1]), "+f"(c[2]), "+f"(c[3])
        : "r"(a[0]), "r"(a[1]), "r"(a[2]), "r"(a[3]), "r"(b[0]), "r"(b[1]));
}

// ---------------- prep kernels ----------------------------------------------
__global__ void k_prep0(const float* __restrict__ W1, const float* __restrict__ W2) {
    int i = blockIdx.x * blockDim.x + threadIdx.x;
    if (i < F_IN * F_H) {
        int k = i >> 7, n = i & 127;
        float v = W1[i];
        __half h = __float2half_rn(v);
        g_W1h[(size_t)n * F_IN + k] = h;
        g_W1l[(size_t)n * F_IN + k] = __float2half_rn(v - __half2float(h));
    }
    if (i < F_H * F_OUT) {
        int k = i / F_OUT, n = i % F_OUT;
        float v = W2[i];
        __half h = __float2half_rn(v);
        g_W2Th[(size_t)n * F_H + k] = h;
        g_W2Tl[(size_t)n * F_H + k] = __float2half_rn(v - __half2float(h));
    }
    if (i < N_NODES) g_cnt[i] = 0;
}
__global__ void k_count(const int* __restrict__ ei) {
    int e = blockIdx.x * blockDim.x + threadIdx.x;
    if (e < N_EDGES) atomicAdd(&g_cnt[ei[N_EDGES + e]], 1);
}
__global__ void k_scan1() {
    __shared__ int s[SCAN_B];
    int i = blockIdx.x * SCAN_B + threadIdx.x;
    int v = (i < N_NODES) ? g_cnt[i] : 0;
    if (i < N_NODES) {
        float d = (float)(v + 1);
        float r = rsqrtf(d);
        g_dinv[i]  = r;
        g_selfc[i] = (1.0f - ALPHA) * r * r;
    }
    s[threadIdx.x] = v;
    __syncthreads();
#pragma unroll
    for (int off = 1; off < SCAN_B; off <<= 1) {
        int t = (threadIdx.x >= off) ? s[threadIdx.x - off] : 0;
        __syncthreads();
        s[threadIdx.x] += t;
        __syncthreads();
    }
    if (i < N_NODES) g_offs[i] = s[threadIdx.x] - v;
    if (threadIdx.x == SCAN_B - 1) g_bsum[blockIdx.x] = s[SCAN_B - 1];
}
__global__ void k_scan2() {
    __shared__ int s[256];
    int t = threadIdx.x;
    int v = (t < NBLK) ? g_bsum[t] : 0;
    s[t] = v;
    __syncthreads();
#pragma unroll
    for (int off = 1; off < 256; off <<= 1) {
        int u = (t >= off) ? s[t - off] : 0;
        __syncthreads();
        s[t] += u;
        __syncthreads();
    }
    if (t < NBLK) g_bsum2[t] = s[t] - v;
    if (t == 0) g_offs[N_NODES] = s[255];
}
__global__ void k_scan3() {
    int i = blockIdx.x * blockDim.x + threadIdx.x;
    if (i >= N_NODES) return;
    int o = g_offs[i] + g_bsum2[i / SCAN_B];
    g_offs[i]   = o;
    g_cursor[i] = o;
}
__global__ void k_fill(const int* __restrict__ ei) {
    int e = blockIdx.x * blockDim.x + threadIdx.x;
    if (e >= N_EDGES) return;
    int r = ei[e];
    int c = ei[N_EDGES + e];
    int pos = atomicAdd(&g_cursor[c], 1);
    float w = (1.0f - ALPHA) * g_dinv[r] * g_dinv[c];
    uint32_t wb = (uint32_t)__half_as_ushort(__float2half_rn(w)) & 0x7FFFu;
    g_csr[pos] = ((uint32_t)r << 15) | wb;
}

// ---------------- GEMM1: h1 = fp16(relu(x @ W1 + b1)), fp16x3 MMA -----------
#define G1ST 40
__global__ void __launch_bounds__(256) k_gemm1(const float* __restrict__ x,
                                               const float* __restrict__ b1) {
    __shared__ __half xs_h[128 * G1ST], xs_l[128 * G1ST];
    __shared__ __half ws_h[128 * G1ST], ws_l[128 * G1ST];
    uint32_t wsh32 = smem_u32(ws_h), wsl32 = smem_u32(ws_l);

    int tid = threadIdx.x;
    int wid = tid >> 5, lid = tid & 31;
    int g = lid >> 2, tig = lid & 3;
    int wm = wid & 3, wn = wid >> 2;
    int row0 = blockIdx.x * 128;

    float acc[2][8][4];
#pragma unroll
    for (int mt = 0; mt < 2; mt++)
#pragma unroll
        for (int nt = 0; nt < 8; nt++)
#pragma unroll
            for (int i = 0; i < 4; i++) acc[mt][nt][i] = 0.0f;

    for (int kt = 0; kt < 16; kt++) {
#pragma unroll
        for (int i = 0; i < 2; i++) {
            int slot = tid + i * 256;
            int n = slot >> 2, c = slot & 3;
            cp16(wsh32 + (n * G1ST + c * 8) * 2, &g_W1h[(size_t)n * F_IN + kt * 32 + c * 8]);
            cp16(wsl32 + (n * G1ST + c * 8) * 2, &g_W1l[(size_t)n * F_IN + kt * 32 + c * 8]);
        }
        asm volatile("cp.async.commit_group;" ::: "memory");
#pragma unroll
        for (int i = 0; i < 4; i++) {
            int slot = tid + i * 256;
            int m = slot >> 3, c4 = slot & 7;
            int grow = row0 + m; if (grow >= N_NODES) grow = N_NODES - 1;
            float4 v = *(const float4*)&x[(size_t)grow * F_IN + kt * 32 + c4 * 4];
            __half hx0 = __float2half_rn(v.x), hx1 = __float2half_rn(v.y);
            __half hx2 = __float2half_rn(v.z), hx3 = __float2half_rn(v.w);
            __half lx0 = __float2half_rn(v.x - __half2float(hx0));
            __half lx1 = __float2half_rn(v.y - __half2float(hx1));
            __half lx2 = __float2half_rn(v.z - __half2float(hx2));
            __half lx3 = __float2half_rn(v.w - __half2float(hx3));
            __half* ph = &xs_h[m * G1ST + c4 * 4];
            __half* pl = &xs_l[m * G1ST + c4 * 4];
            *(__half2*)ph       = __halves2half2(hx0, hx1);
            *(__half2*)(ph + 2) = __halves2half2(hx2, hx3);
            *(__half2*)pl       = __halves2half2(lx0, lx1);
            *(__half2*)(pl + 2) = __halves2half2(lx2, lx3);
        }
        asm volatile("cp.async.wait_group 0;" ::: "memory");
        __syncthreads();

#pragma unroll
        for (int ks = 0; ks < 2; ks++) {
            int kk = ks * 16;
            uint32_t ah[2][4], al[2][4];
#pragma unroll
            for (int mt = 0; mt < 2; mt++) {
                int m = wm * 32 + mt * 16 + g;
                ah[mt][0] = *(uint32_t*)&xs_h[m * G1ST + kk + 2 * tig];
                ah[mt][1] = *(uint32_t*)&xs_h[(m + 8) * G1ST + kk + 2 * tig];
                ah[mt][2] = *(uint32_t*)&xs_h[m * G1ST + kk + 8 + 2 * tig];
                ah[mt][3] = *(uint32_t*)&xs_h[(m + 8) * G1ST + kk + 8 + 2 * tig];
                al[mt][0] = *(uint32_t*)&xs_l[m * G1ST + kk + 2 * tig];
                al[mt][1] = *(uint32_t*)&xs_l[(m + 8) * G1ST + kk + 2 * tig];
                al[mt][2] = *(uint32_t*)&xs_l[m * G1ST + kk + 8 + 2 * tig];
                al[mt][3] = *(uint32_t*)&xs_l[(m + 8) * G1ST + kk + 8 + 2 * tig];
            }
#pragma unroll
            for (int nt = 0; nt < 8; nt++) {
                int n = wn * 64 + nt * 8 + g;
                uint32_t bh[2], bl[2];
                bh[0] = *(uint32_t*)&ws_h[n * G1ST + kk + 2 * tig];
                bh[1] = *(uint32_t*)&ws_h[n * G1ST + kk + 8 + 2 * tig];
                bl[0] = *(uint32_t*)&ws_l[n * G1ST + kk + 2 * tig];
                bl[1] = *(uint32_t*)&ws_l[n * G1ST + kk + 8 + 2 * tig];
#pragma unroll
                for (int mt = 0; mt < 2; mt++) {
                    mma_f16(acc[mt][nt], ah[mt], bh);
                    mma_f16(acc[mt][nt], ah[mt], bl);
                    mma_f16(acc[mt][nt], al[mt], bh);
                }
            }
        }
        __syncthreads();
    }

#pragma unroll
    for (int nt = 0; nt < 8; nt++) {
        int col = wn * 64 + nt * 8 + tig * 2;
        float2 bb = *(const float2*)&b1[col];
#pragma unroll
        for (int mt = 0; mt < 2; mt++) {
            int r0 = row0 + wm * 32 + mt * 16 + g;
            if (r0 < N_NODES) {
                float ox = acc[mt][nt][0] + bb.x, oy = acc[mt][nt][1] + bb.y;
                ox = ox > 0.f ? ox : 0.f;  oy = oy > 0.f ? oy : 0.f;
                *(__half2*)&g_h1[(size_t)r0 * F_H + col] = __floats2half2_rn(ox, oy);
            }
            if (r0 + 8 < N_NODES) {
                float ox = acc[mt][nt][2] + bb.x, oy = acc[mt][nt][3] + bb.y;
                ox = ox > 0.f ? ox : 0.f;  oy = oy > 0.f ? oy : 0.f;
                *(__half2*)&g_h1[(size_t)(r0 + 8) * F_H + col] = __floats2half2_rn(ox, oy);
            }
        }
    }
}

// ---------------- GEMM2: h0h = fp16(relu(h1 @ W2 + b2)), fp16 MMA -----------
#define G2ST 136
#define G2SMEM ((128 * G2ST + 2 * F_OUT * G2ST) * 2)
__global__ void __launch_bounds__(256) k_gemm2(const float* __restrict__ b2) {
    extern __shared__ __half sm2[];
    __half* hs = sm2;
    __half* wh = sm2 + 128 * G2ST;
    __half* wl = wh + F_OUT * G2ST;
    uint32_t hs32 = smem_u32(hs), wh32 = smem_u32(wh), wl32 = smem_u32(wl);

    int tid = threadIdx.x;
    int wid = tid >> 5, lid = tid & 31;
    int g = lid >> 2, tig = lid & 3;
    int row0 = blockIdx.x * 128;

#pragma unroll
    for (int i = 0; i < 8; i++) {
        int slot = tid + i * 256;
        int m = slot >> 4, c = slot & 15;
        int grow = row0 + m; if (grow >= N_NODES) grow = N_NODES - 1;
        cp16(hs32 + (m * G2ST + c * 8) * 2, &g_h1[(size_t)grow * F_H + c * 8]);
    }
#pragma unroll
    for (int i = 0; i < 3; i++) {
        int slot = tid + i * 256;
        if (slot < F_OUT * 16) {
            int n = slot >> 4, c = slot & 15;
            cp16(wh32 + (n * G2ST + c * 8) * 2, &g_W2Th[(size_t)n * F_H + c * 8]);
            cp16(wl32 + (n * G2ST + c * 8) * 2, &g_W2Tl[(size_t)n * F_H + c * 8]);
        }
    }
    asm volatile("cp.async.commit_group;" ::: "memory");
    asm volatile("cp.async.wait_group 0;" ::: "memory");
    __syncthreads();

    float acc[5][4];
#pragma unroll
    for (int nt = 0; nt < 5; nt++)
#pragma unroll
        for (int i = 0; i < 4; i++) acc[nt][i] = 0.0f;

#pragma unroll
    for (int ks = 0; ks < 8; ks++) {
        int kk = ks * 16;
        int m = wid * 16 + g;
        uint32_t a[4];
        a[0] = *(uint32_t*)&hs[m * G2ST + kk + 2 * tig];
        a[1] = *(uint32_t*)&hs[(m + 8) * G2ST + kk + 2 * tig];
        a[2] = *(uint32_t*)&hs[m * G2ST + kk + 8 + 2 * tig];
        a[3] = *(uint32_t*)&hs[(m + 8) * G2ST + kk + 8 + 2 * tig];
#pragma unroll
        for (int nt = 0; nt < 5; nt++) {
            int n = nt * 8 + g;
            uint32_t bhv[2], blv[2];
            bhv[0] = *(uint32_t*)&wh[n * G2ST + kk + 2 * tig];
            bhv[1] = *(uint32_t*)&wh[n * G2ST + kk + 8 + 2 * tig];
            blv[0] = *(uint32_t*)&wl[n * G2ST + kk + 2 * tig];
            blv[1] = *(uint32_t*)&wl[n * G2ST + kk + 8 + 2 * tig];
            mma_f16(acc[nt], a, bhv);
            mma_f16(acc[nt], a, blv);
        }
    }

#pragma unroll
    for (int nt = 0; nt < 5; nt++) {
        int col = nt * 8 + tig * 2;
        float2 bb = *(const float2*)&b2[col];
        int r0 = row0 + wid * 16 + g;
        if (r0 < N_NODES) {
            float ox = acc[nt][0] + bb.x, oy = acc[nt][1] + bb.y;
            ox = ox > 0.f ? ox : 0.f;  oy = oy > 0.f ? oy : 0.f;
            *(__half2*)&g_h0h[(size_t)r0 * F_PAD + col] = __floats2half2_rn(ox, oy);
        }
        if (r0 + 8 < N_NODES) {
            float ox = acc[nt][2] + bb.x, oy = acc[nt][3] + bb.y;
            ox = ox > 0.f ? ox : 0.f;  oy = oy > 0.f ? oy : 0.f;
            *(__half2*)&g_h0h[(size_t)(r0 + 8) * F_PAD + col] = __floats2half2_rn(ox, oy);
        }
    }
}

// ---------------- propagation: warp-per-node pull, packed CSR, padded rows --
// 6 groups x 5 lanes per warp; group handles edges e0+group+6k; lane q loads
// uint4 chunk q of the 128B-padded source row (only first 80B real).
#define NPW 8
template <bool LAST>
__global__ void __launch_bounds__(256) k_pull_w(const __half* __restrict__ srcp,
                                                void* __restrict__ dstv) {
    int lane = threadIdx.x & 31;
    int gw   = blockIdx.x * 8 + (threadIdx.x >> 5);
    int n0 = gw * NPW;
    if (n0 >= N_NODES) return;
    int n1 = n0 + NPW; if (n1 > N_NODES) n1 = N_NODES;

    const char* sbase = (const char*)srcp;
    const uint4* s4   = (const uint4*)srcp;
    const uint4* h4   = (const uint4*)g_h0h;
    int group = lane / 5;
    int q     = lane % 5;
    int qb    = q * 16;
    bool act  = lane < 30;

    for (int n = n0; n < n1; n++) {
        int e0 = g_offs[n], e1 = g_offs[n + 1];
        float2 acc[4];
#pragma unroll
        for (int j = 0; j < 4; j++) acc[j] = make_float2(0.f, 0.f);

        if (act) {
            int e = e0 + group;
            for (; e + 18 < e1; e += 24) {
                uint32_t p0 = __ldg(&g_csr[e]);
                uint32_t p1 = __ldg(&g_csr[e + 6]);
                uint32_t p2 = __ldg(&g_csr[e + 12]);
                uint32_t p3 = __ldg(&g_csr[e + 18]);
                uint4 r0 = __ldg((const uint4*)(sbase + (((p0 >> 8) & 0xFFFFFF80u)) + qb));
                uint4 r1 = __ldg((const uint4*)(sbase + (((p1 >> 8) & 0xFFFFFF80u)) + qb));
                uint4 r2 = __ldg((const uint4*)(sbase + (((p2 >> 8) & 0xFFFFFF80u)) + qb));
                uint4 r3 = __ldg((const uint4*)(sbase + (((p3 >> 8) & 0xFFFFFF80u)) + qb));
                float w0 = __half2float(__ushort_as_half((unsigned short)(p0 & 0x7FFFu)));
                float w1 = __half2float(__ushort_as_half((unsigned short)(p1 & 0x7FFFu)));
                float w2 = __half2float(__ushort_as_half((unsigned short)(p2 & 0x7FFFu)));
                float w3 = __half2float(__ushort_as_half((unsigned short)(p3 & 0x7FFFu)));
                const __half2* a0 = (const __half2*)&r0;
                const __half2* a1 = (const __half2*)&r1;
                const __half2* a2 = (const __half2*)&r2;
                const __half2* a3 = (const __half2*)&r3;
#pragma unroll
                for (int j = 0; j < 4; j++) {
                    float2 v0 = __half22float2(a0[j]);
                    float2 v1 = __half22float2(a1[j]);
                    float2 v2 = __half22float2(a2[j]);
                    float2 v3 = __half22float2(a3[j]);
                    acc[j].x = fmaf(w0, v0.x, acc[j].x); acc[j].y = fmaf(w0, v0.y, acc[j].y);
                    acc[j].x = fmaf(w1, v1.x, acc[j].x); acc[j].y = fmaf(w1, v1.y, acc[j].y);
                    acc[j].x = fmaf(w2, v2.x, acc[j].x); acc[j].y = fmaf(w2, v2.y, acc[j].y);
                    acc[j].x = fmaf(w3, v3.x, acc[j].x); acc[j].y = fmaf(w3, v3.y, acc[j].y);
                }
            }
            for (; e < e1; e += 6) {
                uint32_t p = __ldg(&g_csr[e]);
                uint4 r = __ldg((const uint4*)(sbase + (((p >> 8) & 0xFFFFFF80u)) + qb));
                float w = __half2float(__ushort_as_half((unsigned short)(p & 0x7FFFu)));
                const __half2* a = (const __half2*)&r;
#pragma unroll
                for (int j = 0; j < 4; j++) {
                    float2 v = __half22float2(a[j]);
                    acc[j].x = fmaf(w, v.x, acc[j].x);
                    acc[j].y = fmaf(w, v.y, acc[j].y);
                }
            }
        }

        // reduce 6 groups: round1 (+15), then snapshot (+5, +10)
#pragma unroll
        for (int j = 0; j < 4; j++) {
            acc[j].x += __shfl_sync(0xFFFFFFFFu, acc[j].x, (lane + 15) & 31);
            acc[j].y += __shfl_sync(0xFFFFFFFFu, acc[j].y, (lane + 15) & 31);
        }
#pragma unroll
        for (int j = 0; j < 4; j++) {
            float tx1 = __shfl_sync(0xFFFFFFFFu, acc[j].x, (lane + 5) & 31);
            float ty1 = __shfl_sync(0xFFFFFFFFu, acc[j].y, (lane + 5) & 31);
            float tx2 = __shfl_sync(0xFFFFFFFFu, acc[j].x, (lane + 10) & 31);
            float ty2 = __shfl_sync(0xFFFFFFFFu, acc[j].y, (lane + 10) & 31);
            acc[j].x += tx1 + tx2;
            acc[j].y += ty1 + ty2;
        }

        if (lane < 5) {
            float sc = g_selfc[n];
            uint4 hraw = h4[n * 8 + lane];
            uint4 sraw = s4[n * 8 + lane];
            const __half2* hh = (const __half2*)&hraw;
            const __half2* sh = (const __half2*)&sraw;
#pragma unroll
            for (int j = 0; j < 4; j++) {
                float2 hv = __half22float2(hh[j]);
                float2 sv = __half22float2(sh[j]);
                acc[j].x += fmaf(sc, sv.x, ALPHA * hv.x);
                acc[j].y += fmaf(sc, sv.y, ALPHA * hv.y);
            }
            if (LAST) {
                float* out = (float*)dstv;
                float4 o0 = make_float4(acc[0].x, acc[0].y, acc[1].x, acc[1].y);
                float4 o1 = make_float4(acc[2].x, acc[2].y, acc[3].x, acc[3].y);
                *(float4*)&out[(size_t)n * F_OUT + lane * 8]     = o0;
                *(float4*)&out[(size_t)n * F_OUT + lane * 8 + 4] = o1;
            } else {
                uint4 o;
                __half2* oh = (__half2*)&o;
#pragma unroll
                for (int j = 0; j < 4; j++) oh[j] = __float22half2_rn(acc[j]);
                ((uint4*)dstv)[n * 8 + lane] = o;
            }
        }
    }
}

// ---------------- launcher ---------------------------------------------------
extern "C" void kernel_launch(void* const* d_in, const int* in_sizes, int n_in,
                              void* d_out, int out_size) {
    const float* x  = (const float*)d_in[0];
    const int*   ei = (const int*)  d_in[1];
    const float* W1 = (const float*)d_in[2];
    const float* b1 = (const float*)d_in[3];
    const float* W2 = (const float*)d_in[4];
    const float* b2 = (const float*)d_in[5];

    __half *zA, *zB, *h0h;
    cudaGetSymbolAddress((void**)&zA,  g_zhA);
    cudaGetSymbolAddress((void**)&zB,  g_zhB);
    cudaGetSymbolAddress((void**)&h0h, g_h0h);

    cudaFuncSetAttribute(k_gemm2, cudaFuncAttributeMaxDynamicSharedMemorySize, G2SMEM);

    // CSR build + weight prep
    k_prep0<<<(N_NODES + 255) / 256, 256>>>(W1, W2);
    k_count<<<(N_EDGES + 255) / 256, 256>>>(ei);
    k_scan1<<<NBLK, SCAN_B>>>();
    k_scan2<<<1, 256>>>();
    k_scan3<<<(N_NODES + 255) / 256, 256>>>();
    k_fill <<<(N_EDGES + 255) / 256, 256>>>(ei);

    // MLP encoder (fp16 tensor-core MMA)
    k_gemm1<<<(N_NODES + 127) / 128, 256>>>(x, b1);
    k_gemm2<<<(N_NODES + 127) / 128, 256, G2SMEM>>>(b2);

    // APPNP propagation (warp-per-node pull, fp16 z, packed CSR)
    int nwarps = (N_NODES + NPW - 1) / NPW;
    int pgrid  = (nwarps + 7) / 8;
    const __half* src = h0h;
    for (int it = 0; it < K_ITERS - 1; it++) {
        __half* dst = (it & 1) ? zB : zA;
        k_pull_w<false><<<pgrid, 256>>>(src, dst);
        src = dst;
    }
    k_pull_w<true><<<pgrid, 256>>>(src, d_out);
}